// round 5
// baseline (speedup 1.0000x reference)
#include <cuda_runtime.h>
#include <cuda_bf16.h>

typedef unsigned int u32;

#define TPB 320
#define NW  10   // warps per CTA

// SMEM: B-frag bank 64KB | consts 2KB | per-warp h1/hd1 stash 80KB
#define CONST_OFF 65536
#define STASH_OFF (65536 + 2048)
#define SMEM_BYTES (STASH_OFF + TPB * 64 * 4)   // 149504

__device__ __forceinline__ float ftanh(float x) {
    float e; asm("ex2.approx.f32 %0, %1;" : "=f"(e) : "f"(x * 2.8853900817779268f));
    float r; asm("rcp.approx.f32 %0, %1;" : "=f"(r) : "f"(e + 1.0f));
    return fmaf(-2.0f, r, 1.0f);
}

// split (a,b) -> packed bf16x2 hi + residual lo
__device__ __forceinline__ void split2(float a, float b, u32 &hi, u32 &lo) {
    __nv_bfloat162 h2 = __floats2bfloat162_rn(a, b);
    hi = *reinterpret_cast<u32*>(&h2);
    float ar = __bfloat162float(__low2bfloat16(h2));
    float br = __bfloat162float(__high2bfloat16(h2));
    __nv_bfloat162 l2 = __floats2bfloat162_rn(a - ar, b - br);
    lo = *reinterpret_cast<u32*>(&l2);
}

__device__ __forceinline__ void mma16816(float* d, const u32* a, u32 b0, u32 b1) {
    asm volatile(
        "mma.sync.aligned.m16n8k16.row.col.f32.bf16.bf16.f32 "
        "{%0,%1,%2,%3},{%4,%5,%6,%7},{%8,%9},{%0,%1,%2,%3};"
        : "+f"(d[0]), "+f"(d[1]), "+f"(d[2]), "+f"(d[3])
        : "r"(a[0]), "r"(a[1]), "r"(a[2]), "r"(a[3]), "r"(b0), "r"(b1));
}

// One GEMM stage: [16,64] x [64,64] for value (zacc) and tangent (dacc),
// 3-term bf16 split. n-tiles processed in pairs with z/d streams alternated
// so writes into the same accumulator are 4 MMAs apart (no RAW back-to-back).
#define RUN_STAGE(S) do {                                                     \
    _Pragma("unroll")                                                         \
    for (int nt = 0; nt < 8; nt++) {                                          \
        _Pragma("unroll")                                                     \
        for (int j = 0; j < 4; j++) { zacc[nt][j] = 0.f; dacc[nt][j] = 0.f; } \
    }                                                                         \
    _Pragma("unroll")                                                         \
    for (int kt = 0; kt < 4; kt++) {                                          \
        _Pragma("unroll")                                                     \
        for (int np = 0; np < 4; np++) {                                      \
            uint4 bfa = bfr[(((S) * 4 + kt) * 8 + 2 * np) * 32 + lane];       \
            uint4 bfb = bfr[(((S) * 4 + kt) * 8 + 2 * np + 1) * 32 + lane];   \
            mma16816(zacc[2*np],   Ah[kt], bfa.x, bfa.y);                     \
            mma16816(zacc[2*np+1], Ah[kt], bfb.x, bfb.y);                     \
            mma16816(dacc[2*np],   Th[kt], bfa.x, bfa.y);                     \
            mma16816(dacc[2*np+1], Th[kt], bfb.x, bfb.y);                     \
            mma16816(zacc[2*np],   Ah[kt], bfa.z, bfa.w);                     \
            mma16816(zacc[2*np+1], Ah[kt], bfb.z, bfb.w);                     \
            mma16816(dacc[2*np],   Th[kt], bfa.z, bfa.w);                     \
            mma16816(dacc[2*np+1], Th[kt], bfb.z, bfb.w);                     \
            mma16816(zacc[2*np],   Al[kt], bfa.x, bfa.y);                     \
            mma16816(zacc[2*np+1], Al[kt], bfb.x, bfb.y);                     \
            mma16816(dacc[2*np],   Tl[kt], bfa.x, bfa.y);                     \
            mma16816(dacc[2*np+1], Tl[kt], bfb.x, bfb.y);                     \
        }                                                                     \
    }                                                                         \
} while (0)

// D (m16n8) ntiles (2kt,2kt+1) == A (m16k16) ktile kt, reg-for-reg.
#define PACK_AFRAGS() do {                                                    \
    _Pragma("unroll")                                                         \
    for (int kt = 0; kt < 4; kt++) {                                          \
        split2(zacc[2*kt][0],   zacc[2*kt][1],   Ah[kt][0], Al[kt][0]);       \
        split2(zacc[2*kt][2],   zacc[2*kt][3],   Ah[kt][1], Al[kt][1]);       \
        split2(zacc[2*kt+1][0], zacc[2*kt+1][1], Ah[kt][2], Al[kt][2]);       \
        split2(zacc[2*kt+1][2], zacc[2*kt+1][3], Ah[kt][3], Al[kt][3]);       \
        split2(dacc[2*kt][0],   dacc[2*kt][1],   Th[kt][0], Tl[kt][0]);       \
        split2(dacc[2*kt][2],   dacc[2*kt][3],   Th[kt][1], Tl[kt][1]);       \
        split2(dacc[2*kt+1][0], dacc[2*kt+1][1], Th[kt][2], Tl[kt][2]);       \
        split2(dacc[2*kt+1][2], dacc[2*kt+1][3], Th[kt][3], Tl[kt][3]);       \
    }                                                                         \
} while (0)

__global__ void __launch_bounds__(TPB, 1)
lnn_mma(const float2* __restrict__ X,
        const float* __restrict__ W0, const float* __restrict__ b0,
        const float* __restrict__ W1, const float* __restrict__ b1,
        const float* __restrict__ W2, const float* __restrict__ b2,
        const float* __restrict__ W3,
        float2* __restrict__ out, int B, int nchunks)
{
    extern __shared__ __align__(16) char sm[];
    uint4* bfr = (uint4*)sm;
    float* cs = (float*)(sm + CONST_OFF);
    float* w00f = cs;       float* w01f = cs + 64;
    float* b0f  = cs + 128; float* b1f  = cs + 192;
    float* b2f  = cs + 256; float* w3f  = cs + 320;
    float* stash = (float*)(sm + STASH_OFF);

    const int t = threadIdx.x;
    if (t < 64) {
        w00f[t] = W0[t];     w01f[t] = W0[64 + t];
        b0f[t]  = b0[t];     b1f[t]  = b1[t];
        b2f[t]  = b2[t];     w3f[t]  = W3[t];
    }
    // pre-pack weight B-fragments (hi/lo bf16):
    // s0: W1 (F1), s1: W2 (F2), s2: W2^T (B1), s3: W1^T (B0)
    for (int i = t; i < 4096; i += TPB) {
        int ln = i & 31, nt = (i >> 5) & 7, kt = (i >> 8) & 3, s = i >> 10;
        int k0 = kt * 16 + (ln & 3) * 2;
        int n  = nt * 8 + (ln >> 2);
        float v0, v1, v2, v3;
        if (s == 0) {
            v0 = W1[k0*64+n]; v1 = W1[(k0+1)*64+n];
            v2 = W1[(k0+8)*64+n]; v3 = W1[(k0+9)*64+n];
        } else if (s == 1) {
            v0 = W2[k0*64+n]; v1 = W2[(k0+1)*64+n];
            v2 = W2[(k0+8)*64+n]; v3 = W2[(k0+9)*64+n];
        } else if (s == 2) {
            v0 = W2[n*64+k0]; v1 = W2[n*64+k0+1];
            v2 = W2[n*64+k0+8]; v3 = W2[n*64+k0+9];
        } else {
            v0 = W1[n*64+k0]; v1 = W1[n*64+k0+1];
            v2 = W1[n*64+k0+8]; v3 = W1[n*64+k0+9];
        }
        u32 h0, l0, h1, l1;
        split2(v0, v1, h0, l0);
        split2(v2, v3, h1, l1);
        bfr[i] = make_uint4(h0, h1, l0, l1);
    }
    __syncthreads();

    const int lane = t & 31, warp = t >> 5;
    const int qr = lane >> 2;          // row within 8-row group
    const int qc = (lane & 3) * 2;     // col pair base
    // lane-interleaved stash: [warp][idx 0..63][lane]
    float* st = stash + warp * (64 * 32) + lane;

    for (int chunk = blockIdx.x * NW + warp; chunk < nchunks;
         chunk += gridDim.x * NW) {
        const int r0 = chunk * 16 + qr, r1 = r0 + 8;
        float2 x0 = (r0 < B) ? X[r0] : make_float2(0.f, 0.f);
        float2 x1 = (r1 < B) ? X[r1] : make_float2(0.f, 0.f);
        const float q0 = x0.x, v0 = x0.y, q1 = x1.x, v1 = x1.y;

        u32 Ah[4][4], Al[4][4], Th[4][4], Tl[4][4];

        // ===== F0: h0 (value) and hd0 (tangent) as A fragments =====
#pragma unroll
        for (int kt = 0; kt < 4; kt++) {
#pragma unroll
            for (int hh = 0; hh < 2; hh++) {
                int k = kt * 16 + hh * 8 + qc;
                float wa = w00f[k], wb = w00f[k+1];
                float wc = w01f[k], wd = w01f[k+1];
                float ba = b0f[k],  bb = b0f[k+1];
                float z00 = fmaf(q0, wa, fmaf(v0, wc, ba));
                float z01 = fmaf(q0, wb, fmaf(v0, wd, bb));
                float z10 = fmaf(q1, wa, fmaf(v1, wc, ba));
                float z11 = fmaf(q1, wb, fmaf(v1, wd, bb));
                float h00 = ftanh(z00), h01 = ftanh(z01);
                float h10 = ftanh(z10), h11 = ftanh(z11);
                float d00 = fmaf(-h00, h00, 1.f) * wc;
                float d01 = fmaf(-h01, h01, 1.f) * wd;
                float d10 = fmaf(-h10, h10, 1.f) * wc;
                float d11 = fmaf(-h11, h11, 1.f) * wd;
                split2(h00, h01, Ah[kt][hh*2],   Al[kt][hh*2]);
                split2(h10, h11, Ah[kt][hh*2+1], Al[kt][hh*2+1]);
                split2(d00, d01, Th[kt][hh*2],   Tl[kt][hh*2]);
                split2(d10, d11, Th[kt][hh*2+1], Tl[kt][hh*2+1]);
            }
        }

        float zacc[8][4], dacc[8][4];
        RUN_STAGE(0);

        // ===== F1 elementwise: z1 -> h1,hd1 (stash in SMEM) =====
#pragma unroll
        for (int nt = 0; nt < 8; nt++) {
#pragma unroll
            for (int j = 0; j < 4; j++) {
                int col = nt * 8 + qc + (j & 1);
                float h = ftanh(zacc[nt][j] + b1f[col]);
                float u = fmaf(-h, h, 1.f);
                float hd = u * dacc[nt][j];
                st[(nt * 4 + j) * 32]      = h;
                st[(32 + nt * 4 + j) * 32] = hd;
                zacc[nt][j] = h; dacc[nt][j] = hd;
            }
        }
        PACK_AFRAGS();
        RUN_STAGE(1);

        // ===== F2 elementwise: z2 -> d2, dd2 =====
#pragma unroll
        for (int nt = 0; nt < 8; nt++) {
#pragma unroll
            for (int j = 0; j < 4; j++) {
                int col = nt * 8 + qc + (j & 1);
                float h = ftanh(zacc[nt][j] + b2f[col]);
                float u = fmaf(-h, h, 1.f);
                float hd = u * dacc[nt][j];
                float w3v = w3f[col];
                zacc[nt][j] = w3v * u;                 // d2
                dacc[nt][j] = -2.f * w3v * h * hd;     // dd2
            }
        }
        PACK_AFRAGS();
        RUN_STAGE(2);

        // ===== B1 elementwise: g1,gd1 -> d1,dd1 (stash from SMEM) =====
#pragma unroll
        for (int nt = 0; nt < 8; nt++) {
#pragma unroll
            for (int j = 0; j < 4; j++) {
                float g = zacc[nt][j], gd = dacc[nt][j];
                float h  = st[(nt * 4 + j) * 32];
                float hd = st[(32 + nt * 4 + j) * 32];
                float u = fmaf(-h, h, 1.f);
                zacc[nt][j] = g * u;
                dacc[nt][j] = fmaf(gd, u, -2.f * g * h * hd);
            }
        }
        PACK_AFRAGS();
        RUN_STAGE(3);

        // ===== B0 fold: g0,gd0 + recomputed h0 -> per-row partials =====
        float p00 = 0.f, p01 = 0.f, p02 = 0.f;
        float p10 = 0.f, p11 = 0.f, p12 = 0.f;
#pragma unroll
        for (int nt = 0; nt < 8; nt++) {
#pragma unroll
            for (int j = 0; j < 4; j++) {
                int k = nt * 8 + qc + (j & 1);
                int rh = j >> 1;
                float q = rh ? q1 : q0, v = rh ? v1 : v0;
                float wa = w00f[k], wc = w01f[k];
                float z0 = fmaf(q, wa, fmaf(v, wc, b0f[k]));
                float h = ftanh(z0);
                float u = fmaf(-h, h, 1.f);
                float hd = u * wc;
                float g = zacc[nt][j], gd = dacc[nt][j];
                float d0 = g * u;
                float dd0 = fmaf(gd, u, -2.f * g * h * hd);
                if (rh) {
                    p10 = fmaf(d0, wa, p10);
                    p11 = fmaf(dd0, wa, p11);
                    p12 = fmaf(dd0, wc, p12);
                } else {
                    p00 = fmaf(d0, wa, p00);
                    p01 = fmaf(dd0, wa, p01);
                    p02 = fmaf(dd0, wc, p02);
                }
            }
        }
        // reduce across the 4 lanes of each quad (disjoint k's)
#pragma unroll
        for (int m = 1; m <= 2; m <<= 1) {
            p00 += __shfl_xor_sync(0xFFFFFFFFu, p00, m);
            p01 += __shfl_xor_sync(0xFFFFFFFFu, p01, m);
            p02 += __shfl_xor_sync(0xFFFFFFFFu, p02, m);
            p10 += __shfl_xor_sync(0xFFFFFFFFu, p10, m);
            p11 += __shfl_xor_sync(0xFFFFFFFFu, p11, m);
            p12 += __shfl_xor_sync(0xFFFFFFFFu, p12, m);
        }
        if ((lane & 3) == 0) {
            if (r0 < B) {
                float a = (p00 - p01 * v0) / (p02 + 0.1f);
                out[r0] = make_float2(v0, a);
            }
            if (r1 < B) {
                float a = (p10 - p11 * v1) / (p12 + 0.1f);
                out[r1] = make_float2(v1, a);
            }
        }
    }
}

extern "C" void kernel_launch(void* const* d_in, const int* in_sizes, int n_in,
                              void* d_out, int out_size) {
    const float* x  = (const float*)d_in[1];
    const float* W0 = (const float*)d_in[2];
    const float* b0 = (const float*)d_in[3];
    const float* W1 = (const float*)d_in[4];
    const float* b1 = (const float*)d_in[5];
    const float* W2 = (const float*)d_in[6];
    const float* b2 = (const float*)d_in[7];
    const float* W3 = (const float*)d_in[8];

    const int B = in_sizes[1] / 2;
    const int nchunks = (B + 15) / 16;

    int dev = 0, sms = 148;
    cudaGetDevice(&dev);
    cudaDeviceGetAttribute(&sms, cudaDevAttrMultiProcessorCount, dev);
    int grid = (nchunks + NW - 1) / NW;
    if (grid > sms) grid = sms;

    cudaFuncSetAttribute(lnn_mma, cudaFuncAttributeMaxDynamicSharedMemorySize,
                         SMEM_BYTES);
    lnn_mma<<<grid, TPB, SMEM_BYTES>>>((const float2*)x, W0, b0, W1, b1,
                                       W2, b2, W3, (float2*)d_out, B, nchunks);
}

// round 6
// speedup vs baseline: 1.1481x; 1.1481x over previous
#include <cuda_runtime.h>
#include <cuda_bf16.h>

typedef unsigned int u32;

#define TPB 256
#define NW  8   // warps per CTA

// SMEM: B-fragment bank (4 stages x 4 ktiles x 8 ntiles x 32 lanes x uint4)
//       = 4096 uint4 = 64 KB, then 6x64 fp32 consts.
#define SMEM_BYTES (65536 + 6 * 64 * 4)

__device__ __forceinline__ float ftanh(float x) {
    float e; asm("ex2.approx.f32 %0, %1;" : "=f"(e) : "f"(x * 2.8853900817779268f));
    float r; asm("rcp.approx.f32 %0, %1;" : "=f"(r) : "f"(e + 1.0f));
    return fmaf(-2.0f, r, 1.0f);
}

// split (a,b) -> packed bf16x2 hi + residual lo
__device__ __forceinline__ void split2(float a, float b, u32 &hi, u32 &lo) {
    __nv_bfloat162 h2 = __floats2bfloat162_rn(a, b);
    hi = *reinterpret_cast<u32*>(&h2);
    float ar = __bfloat162float(__low2bfloat16(h2));
    float br = __bfloat162float(__high2bfloat16(h2));
    __nv_bfloat162 l2 = __floats2bfloat162_rn(a - ar, b - br);
    lo = *reinterpret_cast<u32*>(&l2);
}

__device__ __forceinline__ void mma16816(float* d, const u32* a, u32 b0, u32 b1) {
    asm volatile(
        "mma.sync.aligned.m16n8k16.row.col.f32.bf16.bf16.f32 "
        "{%0,%1,%2,%3},{%4,%5,%6,%7},{%8,%9},{%0,%1,%2,%3};"
        : "+f"(d[0]), "+f"(d[1]), "+f"(d[2]), "+f"(d[3])
        : "r"(a[0]), "r"(a[1]), "r"(a[2]), "r"(a[3]), "r"(b0), "r"(b1));
}

// One GEMM stage: [16,64] x [64,64] for value (A=Ah/Al -> zacc) and
// tangent (A=Th/Tl -> dacc), 3-term bf16 split. (R3-proven schedule.)
#define RUN_STAGE(S) do {                                                     \
    _Pragma("unroll")                                                         \
    for (int nt = 0; nt < 8; nt++) {                                          \
        _Pragma("unroll")                                                     \
        for (int j = 0; j < 4; j++) { zacc[nt][j] = 0.f; dacc[nt][j] = 0.f; } \
    }                                                                         \
    _Pragma("unroll")                                                         \
    for (int kt = 0; kt < 4; kt++) {                                          \
        _Pragma("unroll")                                                     \
        for (int nt = 0; nt < 8; nt++) {                                      \
            uint4 bf = bfr[(((S) * 4 + kt) * 8 + nt) * 32 + lane];            \
            mma16816(zacc[nt], Ah[kt], bf.x, bf.y);                           \
            mma16816(zacc[nt], Ah[kt], bf.z, bf.w);                           \
            mma16816(zacc[nt], Al[kt], bf.x, bf.y);                           \
            mma16816(dacc[nt], Th[kt], bf.x, bf.y);                           \
            mma16816(dacc[nt], Th[kt], bf.z, bf.w);                           \
            mma16816(dacc[nt], Tl[kt], bf.x, bf.y);                           \
        }                                                                     \
    }                                                                         \
} while (0)

// D (m16n8) ntiles (2kt,2kt+1) == A (m16k16) ktile kt, reg-for-reg.
#define PACK_AFRAGS() do {                                                    \
    _Pragma("unroll")                                                         \
    for (int kt = 0; kt < 4; kt++) {                                          \
        split2(zacc[2*kt][0],   zacc[2*kt][1],   Ah[kt][0], Al[kt][0]);       \
        split2(zacc[2*kt][2],   zacc[2*kt][3],   Ah[kt][1], Al[kt][1]);       \
        split2(zacc[2*kt+1][0], zacc[2*kt+1][1], Ah[kt][2], Al[kt][2]);       \
        split2(zacc[2*kt+1][2], zacc[2*kt+1][3], Ah[kt][3], Al[kt][3]);       \
        split2(dacc[2*kt][0],   dacc[2*kt][1],   Th[kt][0], Tl[kt][0]);       \
        split2(dacc[2*kt][2],   dacc[2*kt][3],   Th[kt][1], Tl[kt][1]);       \
        split2(dacc[2*kt+1][0], dacc[2*kt+1][1], Th[kt][2], Tl[kt][2]);       \
        split2(dacc[2*kt+1][2], dacc[2*kt+1][3], Th[kt][3], Tl[kt][3]);       \
    }                                                                         \
} while (0)

__global__ void __launch_bounds__(TPB, 1)
lnn_mma(const float2* __restrict__ X,
        const float* __restrict__ W0, const float* __restrict__ b0,
        const float* __restrict__ W1, const float* __restrict__ b1,
        const float* __restrict__ W2, const float* __restrict__ b2,
        const float* __restrict__ W3,
        float2* __restrict__ out, int B, int nchunks)
{
    extern __shared__ __align__(16) char sm[];
    uint4* bfr = (uint4*)sm;
    float* cs = (float*)(sm + 65536);
    float* w00f = cs;       float* w01f = cs + 64;
    float* b0f  = cs + 128; float* b1f  = cs + 192;
    float* b2f  = cs + 256; float* w3f  = cs + 320;

    const int t = threadIdx.x;
    if (t < 64) {
        w00f[t] = W0[t];     w01f[t] = W0[64 + t];
        b0f[t]  = b0[t];     b1f[t]  = b1[t];
        b2f[t]  = b2[t];     w3f[t]  = W3[t];
    }
    // pre-pack weight B-fragments (hi/lo bf16):
    // s0: W1 (F1), s1: W2 (F2), s2: W2^T (B1), s3: W1^T (B0)
    for (int i = t; i < 4096; i += TPB) {
        int ln = i & 31, nt = (i >> 5) & 7, kt = (i >> 8) & 3, s = i >> 10;
        int k0 = kt * 16 + (ln & 3) * 2;
        int n  = nt * 8 + (ln >> 2);
        float v0, v1, v2, v3;
        if (s == 0) {
            v0 = W1[k0*64+n]; v1 = W1[(k0+1)*64+n];
            v2 = W1[(k0+8)*64+n]; v3 = W1[(k0+9)*64+n];
        } else if (s == 1) {
            v0 = W2[k0*64+n]; v1 = W2[(k0+1)*64+n];
            v2 = W2[(k0+8)*64+n]; v3 = W2[(k0+9)*64+n];
        } else if (s == 2) {
            v0 = W2[n*64+k0]; v1 = W2[n*64+k0+1];
            v2 = W2[n*64+k0+8]; v3 = W2[n*64+k0+9];
        } else {
            v0 = W1[n*64+k0]; v1 = W1[n*64+k0+1];
            v2 = W1[n*64+k0+8]; v3 = W1[n*64+k0+9];
        }
        u32 h0, l0, h1, l1;
        split2(v0, v1, h0, l0);
        split2(v2, v3, h1, l1);
        bfr[i] = make_uint4(h0, h1, l0, l1);
    }
    __syncthreads();

    const int lane = t & 31, warp = t >> 5;
    const int qr = lane >> 2;          // row within 8-row group
    const int qc = (lane & 3) * 2;     // col pair base

    // ===== phase skew: 2nd warp on each SMSP (warps 4-7) burns ~5K cycles =====
    // Dependent FMA chain (lat 4 x 1280 iters). skew_zero is exactly 0.0f for
    // the finite chain value; added to an output accumulator -> exact no-op.
    float dly = 1.0f;
    const int skew_iters = ((warp >> 2) & 1) * 1280;
#pragma unroll 1
    for (int i = 0; i < skew_iters; i++)
        dly = fmaf(dly, 1.0000001f, 1e-30f);
    const float skew_zero = dly * 0.0f;

    for (int chunk = blockIdx.x * NW + warp; chunk < nchunks;
         chunk += gridDim.x * NW) {
        const int r0 = chunk * 16 + qr, r1 = r0 + 8;
        float2 x0 = (r0 < B) ? X[r0] : make_float2(0.f, 0.f);
        float2 x1 = (r1 < B) ? X[r1] : make_float2(0.f, 0.f);
        const float q0 = x0.x, v0 = x0.y, q1 = x1.x, v1 = x1.y;

        u32 Ah[4][4], Al[4][4], Th[4][4], Tl[4][4];

        // ===== F0: h0 (value) and hd0 (tangent) as A fragments =====
#pragma unroll
        for (int kt = 0; kt < 4; kt++) {
#pragma unroll
            for (int hh = 0; hh < 2; hh++) {
                int k = kt * 16 + hh * 8 + qc;
                float wa = w00f[k], wb = w00f[k+1];
                float wc = w01f[k], wd = w01f[k+1];
                float ba = b0f[k],  bb = b0f[k+1];
                float z00 = fmaf(q0, wa, fmaf(v0, wc, ba));
                float z01 = fmaf(q0, wb, fmaf(v0, wd, bb));
                float z10 = fmaf(q1, wa, fmaf(v1, wc, ba));
                float z11 = fmaf(q1, wb, fmaf(v1, wd, bb));
                float h00 = ftanh(z00), h01 = ftanh(z01);
                float h10 = ftanh(z10), h11 = ftanh(z11);
                float d00 = fmaf(-h00, h00, 1.f) * wc;
                float d01 = fmaf(-h01, h01, 1.f) * wd;
                float d10 = fmaf(-h10, h10, 1.f) * wc;
                float d11 = fmaf(-h11, h11, 1.f) * wd;
                split2(h00, h01, Ah[kt][hh*2],   Al[kt][hh*2]);
                split2(h10, h11, Ah[kt][hh*2+1], Al[kt][hh*2+1]);
                split2(d00, d01, Th[kt][hh*2],   Tl[kt][hh*2]);
                split2(d10, d11, Th[kt][hh*2+1], Tl[kt][hh*2+1]);
            }
        }

        float zacc[8][4], dacc[8][4];
        RUN_STAGE(0);

        // ===== F1 elementwise: z1 -> h1,hd1 (stash in regs, D-aligned) =====
        float h1s[8][4], hd1s[8][4];
#pragma unroll
        for (int nt = 0; nt < 8; nt++) {
#pragma unroll
            for (int j = 0; j < 4; j++) {
                int col = nt * 8 + qc + (j & 1);
                float h = ftanh(zacc[nt][j] + b1f[col]);
                float u = fmaf(-h, h, 1.f);
                float hd = u * dacc[nt][j];
                h1s[nt][j] = h; hd1s[nt][j] = hd;
                zacc[nt][j] = h; dacc[nt][j] = hd;
            }
        }
        PACK_AFRAGS();
        RUN_STAGE(1);

        // ===== F2 elementwise: z2 -> d2, dd2 =====
#pragma unroll
        for (int nt = 0; nt < 8; nt++) {
#pragma unroll
            for (int j = 0; j < 4; j++) {
                int col = nt * 8 + qc + (j & 1);
                float h = ftanh(zacc[nt][j] + b2f[col]);
                float u = fmaf(-h, h, 1.f);
                float hd = u * dacc[nt][j];
                float w3v = w3f[col];
                zacc[nt][j] = w3v * u;                 // d2
                dacc[nt][j] = -2.f * w3v * h * hd;     // dd2
            }
        }
        PACK_AFRAGS();
        RUN_STAGE(2);

        // ===== B1 elementwise: g1,gd1 -> d1,dd1 (uses stashed h1,hd1) =====
#pragma unroll
        for (int nt = 0; nt < 8; nt++) {
#pragma unroll
            for (int j = 0; j < 4; j++) {
                float g = zacc[nt][j], gd = dacc[nt][j];
                float h = h1s[nt][j], hd = hd1s[nt][j];
                float u = fmaf(-h, h, 1.f);
                zacc[nt][j] = g * u;
                dacc[nt][j] = fmaf(gd, u, -2.f * g * h * hd);
            }
        }
        PACK_AFRAGS();
        RUN_STAGE(3);

        // ===== B0 fold: g0,gd0 + recomputed h0 -> per-row partials =====
        float p00 = skew_zero, p01 = 0.f, p02 = 0.f;
        float p10 = 0.f, p11 = 0.f, p12 = 0.f;
#pragma unroll
        for (int nt = 0; nt < 8; nt++) {
#pragma unroll
            for (int j = 0; j < 4; j++) {
                int k = nt * 8 + qc + (j & 1);
                int rh = j >> 1;
                float q = rh ? q1 : q0, v = rh ? v1 : v0;
                float wa = w00f[k], wc = w01f[k];
                float z0 = fmaf(q, wa, fmaf(v, wc, b0f[k]));
                float h = ftanh(z0);
                float u = fmaf(-h, h, 1.f);
                float hd = u * wc;
                float g = zacc[nt][j], gd = dacc[nt][j];
                float d0 = g * u;
                float dd0 = fmaf(gd, u, -2.f * g * h * hd);
                if (rh) {
                    p10 = fmaf(d0, wa, p10);
                    p11 = fmaf(dd0, wa, p11);
                    p12 = fmaf(dd0, wc, p12);
                } else {
                    p00 = fmaf(d0, wa, p00);
                    p01 = fmaf(dd0, wa, p01);
                    p02 = fmaf(dd0, wc, p02);
                }
            }
        }
        // reduce across the 4 lanes of each quad (they hold disjoint k's)
#pragma unroll
        for (int m = 1; m <= 2; m <<= 1) {
            p00 += __shfl_xor_sync(0xFFFFFFFFu, p00, m);
            p01 += __shfl_xor_sync(0xFFFFFFFFu, p01, m);
            p02 += __shfl_xor_sync(0xFFFFFFFFu, p02, m);
            p10 += __shfl_xor_sync(0xFFFFFFFFu, p10, m);
            p11 += __shfl_xor_sync(0xFFFFFFFFu, p11, m);
            p12 += __shfl_xor_sync(0xFFFFFFFFu, p12, m);
        }
        if ((lane & 3) == 0) {
            if (r0 < B) {
                float a = (p00 - p01 * v0) / (p02 + 0.1f);
                out[r0] = make_float2(v0, a);
            }
            if (r1 < B) {
                float a = (p10 - p11 * v1) / (p12 + 0.1f);
                out[r1] = make_float2(v1, a);
            }
        }
    }
}

extern "C" void kernel_launch(void* const* d_in, const int* in_sizes, int n_in,
                              void* d_out, int out_size) {
    const float* x  = (const float*)d_in[1];
    const float* W0 = (const float*)d_in[2];
    const float* b0 = (const float*)d_in[3];
    const float* W1 = (const float*)d_in[4];
    const float* b1 = (const float*)d_in[5];
    const float* W2 = (const float*)d_in[6];
    const float* b2 = (const float*)d_in[7];
    const float* W3 = (const float*)d_in[8];

    const int B = in_sizes[1] / 2;
    const int nchunks = (B + 15) / 16;

    int dev = 0, sms = 148;
    cudaGetDevice(&dev);
    cudaDeviceGetAttribute(&sms, cudaDevAttrMultiProcessorCount, dev);
    int grid = (nchunks + NW - 1) / NW;
    if (grid > sms) grid = sms;

    cudaFuncSetAttribute(lnn_mma, cudaFuncAttributeMaxDynamicSharedMemorySize,
                         SMEM_BYTES);
    lnn_mma<<<grid, TPB, SMEM_BYTES>>>((const float2*)x, W0, b0, W1, b1,
                                       W2, b2, W3, (float2*)d_out, B, nchunks);
}

// round 7
// speedup vs baseline: 1.4099x; 1.2280x over previous
#include <cuda_runtime.h>
#include <cuda_fp16.h>

typedef unsigned int u32;

#define TPB 256
#define NW  8   // warps per CTA

// SMEM: B-fragment bank (4 stages x 4 ktiles x 8 ntiles x 32 lanes x uint2)
//       = 4096 uint2 = 32 KB, then 6x64 fp32 consts.
#define CONST_OFF 32768
#define SMEM_BYTES (CONST_OFF + 6 * 64 * 4)

__device__ __forceinline__ float ftanh(float x) {
    float e; asm("ex2.approx.f32 %0, %1;" : "=f"(e) : "f"(x * 2.8853900817779268f));
    float r; asm("rcp.approx.f32 %0, %1;" : "=f"(r) : "f"(e + 1.0f));
    return fmaf(-2.0f, r, 1.0f);
}

// split (a,b) -> packed fp16x2 hi + residual lo (A-digit split, ~2^-22 exact)
__device__ __forceinline__ void split2h(float a, float b, u32 &hi, u32 &lo) {
    __half2 h2 = __floats2half2_rn(a, b);
    hi = *reinterpret_cast<u32*>(&h2);
    float2 f = __half22float2(h2);
    __half2 l2 = __floats2half2_rn(a - f.x, b - f.y);
    lo = *reinterpret_cast<u32*>(&l2);
}

__device__ __forceinline__ void mma16816(float* d, const u32* a, u32 b0, u32 b1) {
    asm volatile(
        "mma.sync.aligned.m16n8k16.row.col.f32.f16.f16.f32 "
        "{%0,%1,%2,%3},{%4,%5,%6,%7},{%8,%9},{%0,%1,%2,%3};"
        : "+f"(d[0]), "+f"(d[1]), "+f"(d[2]), "+f"(d[3])
        : "r"(a[0]), "r"(a[1]), "r"(a[2]), "r"(a[3]), "r"(b0), "r"(b1));
}

// One GEMM stage: [16,64] x [64,64] for value (Ah/Al -> zacc) and
// tangent (Th/Tl -> dacc). fp16 2-term split: (Ah + Al) x Bh.
#define RUN_STAGE(S) do {                                                     \
    _Pragma("unroll")                                                         \
    for (int nt = 0; nt < 8; nt++) {                                          \
        _Pragma("unroll")                                                     \
        for (int j = 0; j < 4; j++) { zacc[nt][j] = 0.f; dacc[nt][j] = 0.f; } \
    }                                                                         \
    _Pragma("unroll")                                                         \
    for (int kt = 0; kt < 4; kt++) {                                          \
        _Pragma("unroll")                                                     \
        for (int nt = 0; nt < 8; nt++) {                                      \
            uint2 bf = bfr[(((S) * 4 + kt) * 8 + nt) * 32 + lane];            \
            mma16816(zacc[nt], Ah[kt], bf.x, bf.y);                           \
            mma16816(dacc[nt], Th[kt], bf.x, bf.y);                           \
            mma16816(zacc[nt], Al[kt], bf.x, bf.y);                           \
            mma16816(dacc[nt], Tl[kt], bf.x, bf.y);                           \
        }                                                                     \
    }                                                                         \
} while (0)

// D (m16n8) ntiles (2kt,2kt+1) == A (m16k16) ktile kt, reg-for-reg.
#define PACK_AFRAGS() do {                                                    \
    _Pragma("unroll")                                                         \
    for (int kt = 0; kt < 4; kt++) {                                          \
        split2h(zacc[2*kt][0],   zacc[2*kt][1],   Ah[kt][0], Al[kt][0]);      \
        split2h(zacc[2*kt][2],   zacc[2*kt][3],   Ah[kt][1], Al[kt][1]);      \
        split2h(zacc[2*kt+1][0], zacc[2*kt+1][1], Ah[kt][2], Al[kt][2]);      \
        split2h(zacc[2*kt+1][2], zacc[2*kt+1][3], Ah[kt][3], Al[kt][3]);      \
        split2h(dacc[2*kt][0],   dacc[2*kt][1],   Th[kt][0], Tl[kt][0]);      \
        split2h(dacc[2*kt][2],   dacc[2*kt][3],   Th[kt][1], Tl[kt][1]);      \
        split2h(dacc[2*kt+1][0], dacc[2*kt+1][1], Th[kt][2], Tl[kt][2]);      \
        split2h(dacc[2*kt+1][2], dacc[2*kt+1][3], Th[kt][3], Tl[kt][3]);      \
    }                                                                         \
} while (0)

__global__ void __launch_bounds__(TPB, 1)
lnn_mma(const float2* __restrict__ X,
        const float* __restrict__ W0, const float* __restrict__ b0,
        const float* __restrict__ W1, const float* __restrict__ b1,
        const float* __restrict__ W2, const float* __restrict__ b2,
        const float* __restrict__ W3,
        float2* __restrict__ out, int B, int nchunks)
{
    extern __shared__ __align__(16) char sm[];
    uint2* bfr = (uint2*)sm;
    float* cs = (float*)(sm + CONST_OFF);
    float* w00f = cs;       float* w01f = cs + 64;
    float* b0f  = cs + 128; float* b1f  = cs + 192;
    float* b2f  = cs + 256; float* w3f  = cs + 320;

    const int t = threadIdx.x;
    if (t < 64) {
        w00f[t] = W0[t];     w01f[t] = W0[64 + t];
        b0f[t]  = b0[t];     b1f[t]  = b1[t];
        b2f[t]  = b2[t];     w3f[t]  = W3[t];
    }
    // pre-pack weight B-fragments (single fp16):
    // s0: W1 (F1), s1: W2 (F2), s2: W2^T (B1), s3: W1^T (B0)
    for (int i = t; i < 4096; i += TPB) {
        int ln = i & 31, nt = (i >> 5) & 7, kt = (i >> 8) & 3, s = i >> 10;
        int k0 = kt * 16 + (ln & 3) * 2;
        int n  = nt * 8 + (ln >> 2);
        float v0, v1, v2, v3;
        if (s == 0) {
            v0 = W1[k0*64+n]; v1 = W1[(k0+1)*64+n];
            v2 = W1[(k0+8)*64+n]; v3 = W1[(k0+9)*64+n];
        } else if (s == 1) {
            v0 = W2[k0*64+n]; v1 = W2[(k0+1)*64+n];
            v2 = W2[(k0+8)*64+n]; v3 = W2[(k0+9)*64+n];
        } else if (s == 2) {
            v0 = W2[n*64+k0]; v1 = W2[n*64+k0+1];
            v2 = W2[n*64+k0+8]; v3 = W2[n*64+k0+9];
        } else {
            v0 = W1[n*64+k0]; v1 = W1[n*64+k0+1];
            v2 = W1[n*64+k0+8]; v3 = W1[n*64+k0+9];
        }
        __half2 p0 = __floats2half2_rn(v0, v1);
        __half2 p1 = __floats2half2_rn(v2, v3);
        bfr[i] = make_uint2(*reinterpret_cast<u32*>(&p0),
                            *reinterpret_cast<u32*>(&p1));
    }
    __syncthreads();

    const int lane = t & 31, warp = t >> 5;
    const int qr = lane >> 2;          // row within 8-row group
    const int qc = (lane & 3) * 2;     // col pair base

    // phase skew (neutral-to-positive in R6; keep): warps 4-7 delay ~5K cyc
    float dly = 1.0f;
    const int skew_iters = ((warp >> 2) & 1) * 1280;
#pragma unroll 1
    for (int i = 0; i < skew_iters; i++)
        dly = fmaf(dly, 1.0000001f, 1e-30f);
    const float skew_zero = dly * 0.0f;

    for (int chunk = blockIdx.x * NW + warp; chunk < nchunks;
         chunk += gridDim.x * NW) {
        const int r0 = chunk * 16 + qr, r1 = r0 + 8;
        float2 x0 = (r0 < B) ? X[r0] : make_float2(0.f, 0.f);
        float2 x1 = (r1 < B) ? X[r1] : make_float2(0.f, 0.f);
        const float q0 = x0.x, v0 = x0.y, q1 = x1.x, v1 = x1.y;

        u32 Ah[4][4], Al[4][4], Th[4][4], Tl[4][4];

        // ===== F0: h0 (value) and hd0 (tangent) as A fragments =====
#pragma unroll
        for (int kt = 0; kt < 4; kt++) {
#pragma unroll
            for (int hh = 0; hh < 2; hh++) {
                int k = kt * 16 + hh * 8 + qc;
                float wa = w00f[k], wb = w00f[k+1];
                float wc = w01f[k], wd = w01f[k+1];
                float ba = b0f[k],  bb = b0f[k+1];
                float z00 = fmaf(q0, wa, fmaf(v0, wc, ba));
                float z01 = fmaf(q0, wb, fmaf(v0, wd, bb));
                float z10 = fmaf(q1, wa, fmaf(v1, wc, ba));
                float z11 = fmaf(q1, wb, fmaf(v1, wd, bb));
                float h00 = ftanh(z00), h01 = ftanh(z01);
                float h10 = ftanh(z10), h11 = ftanh(z11);
                float d00 = fmaf(-h00, h00, 1.f) * wc;
                float d01 = fmaf(-h01, h01, 1.f) * wd;
                float d10 = fmaf(-h10, h10, 1.f) * wc;
                float d11 = fmaf(-h11, h11, 1.f) * wd;
                split2h(h00, h01, Ah[kt][hh*2],   Al[kt][hh*2]);
                split2h(h10, h11, Ah[kt][hh*2+1], Al[kt][hh*2+1]);
                split2h(d00, d01, Th[kt][hh*2],   Tl[kt][hh*2]);
                split2h(d10, d11, Th[kt][hh*2+1], Tl[kt][hh*2+1]);
            }
        }

        float zacc[8][4], dacc[8][4];
        RUN_STAGE(0);

        // ===== F1 elementwise: z1 -> h1,hd1 (stash in regs, D-aligned) =====
        float h1s[8][4], hd1s[8][4];
#pragma unroll
        for (int nt = 0; nt < 8; nt++) {
#pragma unroll
            for (int j = 0; j < 4; j++) {
                int col = nt * 8 + qc + (j & 1);
                float h = ftanh(zacc[nt][j] + b1f[col]);
                float u = fmaf(-h, h, 1.f);
                float hd = u * dacc[nt][j];
                h1s[nt][j] = h; hd1s[nt][j] = hd;
                zacc[nt][j] = h; dacc[nt][j] = hd;
            }
        }
        PACK_AFRAGS();
        RUN_STAGE(1);

        // ===== F2 elementwise: z2 -> d2, dd2 =====
#pragma unroll
        for (int nt = 0; nt < 8; nt++) {
#pragma unroll
            for (int j = 0; j < 4; j++) {
                int col = nt * 8 + qc + (j & 1);
                float h = ftanh(zacc[nt][j] + b2f[col]);
                float u = fmaf(-h, h, 1.f);
                float hd = u * dacc[nt][j];
                float w3v = w3f[col];
                zacc[nt][j] = w3v * u;                 // d2
                dacc[nt][j] = -2.f * w3v * h * hd;     // dd2
            }
        }
        PACK_AFRAGS();
        RUN_STAGE(2);

        // ===== B1 elementwise: g1,gd1 -> d1,dd1 (uses stashed h1,hd1) =====
#pragma unroll
        for (int nt = 0; nt < 8; nt++) {
#pragma unroll
            for (int j = 0; j < 4; j++) {
                float g = zacc[nt][j], gd = dacc[nt][j];
                float h = h1s[nt][j], hd = hd1s[nt][j];
                float u = fmaf(-h, h, 1.f);
                zacc[nt][j] = g * u;
                dacc[nt][j] = fmaf(gd, u, -2.f * g * h * hd);
            }
        }
        PACK_AFRAGS();
        RUN_STAGE(3);

        // ===== B0 fold: g0,gd0 + recomputed h0 -> per-row partials =====
        float p00 = skew_zero, p01 = 0.f, p02 = 0.f;
        float p10 = 0.f, p11 = 0.f, p12 = 0.f;
#pragma unroll
        for (int nt = 0; nt < 8; nt++) {
#pragma unroll
            for (int j = 0; j < 4; j++) {
                int k = nt * 8 + qc + (j & 1);
                int rh = j >> 1;
                float q = rh ? q1 : q0, v = rh ? v1 : v0;
                float wa = w00f[k], wc = w01f[k];
                float z0 = fmaf(q, wa, fmaf(v, wc, b0f[k]));
                float h = ftanh(z0);
                float u = fmaf(-h, h, 1.f);
                float hd = u * wc;
                float g = zacc[nt][j], gd = dacc[nt][j];
                float d0 = g * u;
                float dd0 = fmaf(gd, u, -2.f * g * h * hd);
                if (rh) {
                    p10 = fmaf(d0, wa, p10);
                    p11 = fmaf(dd0, wa, p11);
                    p12 = fmaf(dd0, wc, p12);
                } else {
                    p00 = fmaf(d0, wa, p00);
                    p01 = fmaf(dd0, wa, p01);
                    p02 = fmaf(dd0, wc, p02);
                }
            }
        }
        // reduce across the 4 lanes of each quad (disjoint k's)
#pragma unroll
        for (int m = 1; m <= 2; m <<= 1) {
            p00 += __shfl_xor_sync(0xFFFFFFFFu, p00, m);
            p01 += __shfl_xor_sync(0xFFFFFFFFu, p01, m);
            p02 += __shfl_xor_sync(0xFFFFFFFFu, p02, m);
            p10 += __shfl_xor_sync(0xFFFFFFFFu, p10, m);
            p11 += __shfl_xor_sync(0xFFFFFFFFu, p11, m);
            p12 += __shfl_xor_sync(0xFFFFFFFFu, p12, m);
        }
        if ((lane & 3) == 0) {
            if (r0 < B) {
                float a = (p00 - p01 * v0) / (p02 + 0.1f);
                out[r0] = make_float2(v0, a);
            }
            if (r1 < B) {
                float a = (p10 - p11 * v1) / (p12 + 0.1f);
                out[r1] = make_float2(v1, a);
            }
        }
    }
}

extern "C" void kernel_launch(void* const* d_in, const int* in_sizes, int n_in,
                              void* d_out, int out_size) {
    const float* x  = (const float*)d_in[1];
    const float* W0 = (const float*)d_in[2];
    const float* b0 = (const float*)d_in[3];
    const float* W1 = (const float*)d_in[4];
    const float* b1 = (const float*)d_in[5];
    const float* W2 = (const float*)d_in[6];
    const float* b2 = (const float*)d_in[7];
    const float* W3 = (const float*)d_in[8];

    const int B = in_sizes[1] / 2;
    const int nchunks = (B + 15) / 16;

    int dev = 0, sms = 148;
    cudaGetDevice(&dev);
    cudaDeviceGetAttribute(&sms, cudaDevAttrMultiProcessorCount, dev);
    int grid = (nchunks + NW - 1) / NW;
    if (grid > sms) grid = sms;

    cudaFuncSetAttribute(lnn_mma, cudaFuncAttributeMaxDynamicSharedMemorySize,
                         SMEM_BYTES);
    lnn_mma<<<grid, TPB, SMEM_BYTES>>>((const float2*)x, W0, b0, W1, b1,
                                       W2, b2, W3, (float2*)d_out, B, nchunks);
}

// round 8
// speedup vs baseline: 1.5987x; 1.1339x over previous
#include <cuda_runtime.h>
#include <cuda_fp16.h>

typedef unsigned int u32;

#define TPB 384
#define NW  12   // warps per CTA

// SMEM: B-fragment bank 32KB | consts 2KB | per-warp h1/hd1 stash 96KB
#define CONST_OFF 32768
#define STASH_OFF (32768 + 2048)
#define SMEM_BYTES (STASH_OFF + TPB * 64 * 4)   // 133120

__device__ __forceinline__ float ftanh(float x) {
    float e; asm("ex2.approx.f32 %0, %1;" : "=f"(e) : "f"(x * 2.8853900817779268f));
    float r; asm("rcp.approx.f32 %0, %1;" : "=f"(r) : "f"(e + 1.0f));
    return fmaf(-2.0f, r, 1.0f);
}

// split (a,b) -> packed fp16x2 hi + residual lo (A-digit split, ~2^-22 exact)
__device__ __forceinline__ void split2h(float a, float b, u32 &hi, u32 &lo) {
    __half2 h2 = __floats2half2_rn(a, b);
    hi = *reinterpret_cast<u32*>(&h2);
    float2 f = __half22float2(h2);
    __half2 l2 = __floats2half2_rn(a - f.x, b - f.y);
    lo = *reinterpret_cast<u32*>(&l2);
}

__device__ __forceinline__ void mma16816(float* d, const u32* a, u32 b0, u32 b1) {
    asm volatile(
        "mma.sync.aligned.m16n8k16.row.col.f32.f16.f16.f32 "
        "{%0,%1,%2,%3},{%4,%5,%6,%7},{%8,%9},{%0,%1,%2,%3};"
        : "+f"(d[0]), "+f"(d[1]), "+f"(d[2]), "+f"(d[3])
        : "r"(a[0]), "r"(a[1]), "r"(a[2]), "r"(a[3]), "r"(b0), "r"(b1));
}

// One GEMM stage: [16,64] x [64,64] value (Ah/Al) + tangent (Th/Tl),
// fp16 2-term split: (Ah + Al) x Bh.  (R7-proven schedule.)
#define RUN_STAGE(S) do {                                                     \
    _Pragma("unroll")                                                         \
    for (int nt = 0; nt < 8; nt++) {                                          \
        _Pragma("unroll")                                                     \
        for (int j = 0; j < 4; j++) { zacc[nt][j] = 0.f; dacc[nt][j] = 0.f; } \
    }                                                                         \
    _Pragma("unroll")                                                         \
    for (int kt = 0; kt < 4; kt++) {                                          \
        _Pragma("unroll")                                                     \
        for (int nt = 0; nt < 8; nt++) {                                      \
            uint2 bf = bfr[(((S) * 4 + kt) * 8 + nt) * 32 + lane];            \
            mma16816(zacc[nt], Ah[kt], bf.x, bf.y);                           \
            mma16816(dacc[nt], Th[kt], bf.x, bf.y);                           \
            mma16816(zacc[nt], Al[kt], bf.x, bf.y);                           \
            mma16816(dacc[nt], Tl[kt], bf.x, bf.y);                           \
        }                                                                     \
    }                                                                         \
} while (0)

// D (m16n8) ntiles (2kt,2kt+1) == A (m16k16) ktile kt, reg-for-reg.
#define PACK_AFRAGS() do {                                                    \
    _Pragma("unroll")                                                         \
    for (int kt = 0; kt < 4; kt++) {                                          \
        split2h(zacc[2*kt][0],   zacc[2*kt][1],   Ah[kt][0], Al[kt][0]);      \
        split2h(zacc[2*kt][2],   zacc[2*kt][3],   Ah[kt][1], Al[kt][1]);      \
        split2h(zacc[2*kt+1][0], zacc[2*kt+1][1], Ah[kt][2], Al[kt][2]);      \
        split2h(zacc[2*kt+1][2], zacc[2*kt+1][3], Ah[kt][3], Al[kt][3]);      \
        split2h(dacc[2*kt][0],   dacc[2*kt][1],   Th[kt][0], Tl[kt][0]);      \
        split2h(dacc[2*kt][2],   dacc[2*kt][3],   Th[kt][1], Tl[kt][1]);      \
        split2h(dacc[2*kt+1][0], dacc[2*kt+1][1], Th[kt][2], Tl[kt][2]);      \
        split2h(dacc[2*kt+1][2], dacc[2*kt+1][3], Th[kt][3], Tl[kt][3]);      \
    }                                                                         \
} while (0)

__global__ void __launch_bounds__(TPB, 1)
lnn_mma(const float2* __restrict__ X,
        const float* __restrict__ W0, const float* __restrict__ b0,
        const float* __restrict__ W1, const float* __restrict__ b1,
        const float* __restrict__ W2, const float* __restrict__ b2,
        const float* __restrict__ W3,
        float2* __restrict__ out, int B, int nchunks)
{
    extern __shared__ __align__(16) char sm[];
    uint2* bfr = (uint2*)sm;
    float* cs = (float*)(sm + CONST_OFF);
    float* w00f = cs;       float* w01f = cs + 64;
    float* b0f  = cs + 128; float* b1f  = cs + 192;
    float* b2f  = cs + 256; float* w3f  = cs + 320;
    float* stash = (float*)(sm + STASH_OFF);

    const int t = threadIdx.x;
    if (t < 64) {
        w00f[t] = W0[t];     w01f[t] = W0[64 + t];
        b0f[t]  = b0[t];     b1f[t]  = b1[t];
        b2f[t]  = b2[t];     w3f[t]  = W3[t];
    }
    // pre-pack weight B-fragments (single fp16):
    // s0: W1 (F1), s1: W2 (F2), s2: W2^T (B1), s3: W1^T (B0)
    for (int i = t; i < 4096; i += TPB) {
        int ln = i & 31, nt = (i >> 5) & 7, kt = (i >> 8) & 3, s = i >> 10;
        int k0 = kt * 16 + (ln & 3) * 2;
        int n  = nt * 8 + (ln >> 2);
        float v0, v1, v2, v3;
        if (s == 0) {
            v0 = W1[k0*64+n]; v1 = W1[(k0+1)*64+n];
            v2 = W1[(k0+8)*64+n]; v3 = W1[(k0+9)*64+n];
        } else if (s == 1) {
            v0 = W2[k0*64+n]; v1 = W2[(k0+1)*64+n];
            v2 = W2[(k0+8)*64+n]; v3 = W2[(k0+9)*64+n];
        } else if (s == 2) {
            v0 = W2[n*64+k0]; v1 = W2[n*64+k0+1];
            v2 = W2[n*64+k0+8]; v3 = W2[n*64+k0+9];
        } else {
            v0 = W1[n*64+k0]; v1 = W1[n*64+k0+1];
            v2 = W1[n*64+k0+8]; v3 = W1[n*64+k0+9];
        }
        __half2 p0 = __floats2half2_rn(v0, v1);
        __half2 p1 = __floats2half2_rn(v2, v3);
        bfr[i] = make_uint2(*reinterpret_cast<u32*>(&p0),
                            *reinterpret_cast<u32*>(&p1));
    }
    __syncthreads();

    const int lane = t & 31, warp = t >> 5;
    const int qr = lane >> 2;          // row within 8-row group
    const int qc = (lane & 3) * 2;     // col pair base
    // lane-interleaved per-warp stash: [warp][idx 0..63][lane]
    float* st = stash + warp * (64 * 32) + lane;

    for (int chunk = blockIdx.x * NW + warp; chunk < nchunks;
         chunk += gridDim.x * NW) {
        const int r0 = chunk * 16 + qr, r1 = r0 + 8;
        float2 x0 = (r0 < B) ? X[r0] : make_float2(0.f, 0.f);
        float2 x1 = (r1 < B) ? X[r1] : make_float2(0.f, 0.f);
        const float q0 = x0.x, v0 = x0.y, q1 = x1.x, v1 = x1.y;

        u32 Ah[4][4], Al[4][4], Th[4][4], Tl[4][4];

        // ===== F0: h0 (value) and hd0 (tangent) as A fragments =====
#pragma unroll
        for (int kt = 0; kt < 4; kt++) {
#pragma unroll
            for (int hh = 0; hh < 2; hh++) {
                int k = kt * 16 + hh * 8 + qc;
                float wa = w00f[k], wb = w00f[k+1];
                float wc = w01f[k], wd = w01f[k+1];
                float ba = b0f[k],  bb = b0f[k+1];
                float z00 = fmaf(q0, wa, fmaf(v0, wc, ba));
                float z01 = fmaf(q0, wb, fmaf(v0, wd, bb));
                float z10 = fmaf(q1, wa, fmaf(v1, wc, ba));
                float z11 = fmaf(q1, wb, fmaf(v1, wd, bb));
                float h00 = ftanh(z00), h01 = ftanh(z01);
                float h10 = ftanh(z10), h11 = ftanh(z11);
                float d00 = fmaf(-h00, h00, 1.f) * wc;
                float d01 = fmaf(-h01, h01, 1.f) * wd;
                float d10 = fmaf(-h10, h10, 1.f) * wc;
                float d11 = fmaf(-h11, h11, 1.f) * wd;
                split2h(h00, h01, Ah[kt][hh*2],   Al[kt][hh*2]);
                split2h(h10, h11, Ah[kt][hh*2+1], Al[kt][hh*2+1]);
                split2h(d00, d01, Th[kt][hh*2],   Tl[kt][hh*2]);
                split2h(d10, d11, Th[kt][hh*2+1], Tl[kt][hh*2+1]);
            }
        }

        float zacc[8][4], dacc[8][4];
        RUN_STAGE(0);

        // ===== F1 elementwise: z1 -> h1,hd1 (stash in SMEM) =====
#pragma unroll
        for (int nt = 0; nt < 8; nt++) {
#pragma unroll
            for (int j = 0; j < 4; j++) {
                int col = nt * 8 + qc + (j & 1);
                float h = ftanh(zacc[nt][j] + b1f[col]);
                float u = fmaf(-h, h, 1.f);
                float hd = u * dacc[nt][j];
                st[(nt * 4 + j) * 32]      = h;
                st[(32 + nt * 4 + j) * 32] = hd;
                zacc[nt][j] = h; dacc[nt][j] = hd;
            }
        }
        PACK_AFRAGS();
        RUN_STAGE(1);

        // ===== F2 elementwise: z2 -> d2, dd2 =====
#pragma unroll
        for (int nt = 0; nt < 8; nt++) {
#pragma unroll
            for (int j = 0; j < 4; j++) {
                int col = nt * 8 + qc + (j & 1);
                float h = ftanh(zacc[nt][j] + b2f[col]);
                float u = fmaf(-h, h, 1.f);
                float hd = u * dacc[nt][j];
                float w3v = w3f[col];
                zacc[nt][j] = w3v * u;                 // d2
                dacc[nt][j] = -2.f * w3v * h * hd;     // dd2
            }
        }
        PACK_AFRAGS();
        RUN_STAGE(2);

        // ===== B1 elementwise: g1,gd1 -> d1,dd1 (stash from SMEM) =====
#pragma unroll
        for (int nt = 0; nt < 8; nt++) {
#pragma unroll
            for (int j = 0; j < 4; j++) {
                float g = zacc[nt][j], gd = dacc[nt][j];
                float h  = st[(nt * 4 + j) * 32];
                float hd = st[(32 + nt * 4 + j) * 32];
                float u = fmaf(-h, h, 1.f);
                zacc[nt][j] = g * u;
                dacc[nt][j] = fmaf(gd, u, -2.f * g * h * hd);
            }
        }
        PACK_AFRAGS();
        RUN_STAGE(3);

        // ===== B0 fold: g0,gd0 + recomputed h0 -> per-row partials =====
        float p00 = 0.f, p01 = 0.f, p02 = 0.f;
        float p10 = 0.f, p11 = 0.f, p12 = 0.f;
#pragma unroll
        for (int nt = 0; nt < 8; nt++) {
#pragma unroll
            for (int j = 0; j < 4; j++) {
                int k = nt * 8 + qc + (j & 1);
                int rh = j >> 1;
                float q = rh ? q1 : q0, v = rh ? v1 : v0;
                float wa = w00f[k], wc = w01f[k];
                float z0 = fmaf(q, wa, fmaf(v, wc, b0f[k]));
                float h = ftanh(z0);
                float u = fmaf(-h, h, 1.f);
                float hd = u * wc;
                float g = zacc[nt][j], gd = dacc[nt][j];
                float d0 = g * u;
                float dd0 = fmaf(gd, u, -2.f * g * h * hd);
                if (rh) {
                    p10 = fmaf(d0, wa, p10);
                    p11 = fmaf(dd0, wa, p11);
                    p12 = fmaf(dd0, wc, p12);
                } else {
                    p00 = fmaf(d0, wa, p00);
                    p01 = fmaf(dd0, wa, p01);
                    p02 = fmaf(dd0, wc, p02);
                }
            }
        }
        // reduce across the 4 lanes of each quad (disjoint k's)
#pragma unroll
        for (int m = 1; m <= 2; m <<= 1) {
            p00 += __shfl_xor_sync(0xFFFFFFFFu, p00, m);
            p01 += __shfl_xor_sync(0xFFFFFFFFu, p01, m);
            p02 += __shfl_xor_sync(0xFFFFFFFFu, p02, m);
            p10 += __shfl_xor_sync(0xFFFFFFFFu, p10, m);
            p11 += __shfl_xor_sync(0xFFFFFFFFu, p11, m);
            p12 += __shfl_xor_sync(0xFFFFFFFFu, p12, m);
        }
        if ((lane & 3) == 0) {
            if (r0 < B) {
                float a = (p00 - p01 * v0) / (p02 + 0.1f);
                out[r0] = make_float2(v0, a);
            }
            if (r1 < B) {
                float a = (p10 - p11 * v1) / (p12 + 0.1f);
                out[r1] = make_float2(v1, a);
            }
        }
    }
}

extern "C" void kernel_launch(void* const* d_in, const int* in_sizes, int n_in,
                              void* d_out, int out_size) {
    const float* x  = (const float*)d_in[1];
    const float* W0 = (const float*)d_in[2];
    const float* b0 = (const float*)d_in[3];
    const float* W1 = (const float*)d_in[4];
    const float* b1 = (const float*)d_in[5];
    const float* W2 = (const float*)d_in[6];
    const float* b2 = (const float*)d_in[7];
    const float* W3 = (const float*)d_in[8];

    const int B = in_sizes[1] / 2;
    const int nchunks = (B + 15) / 16;

    int dev = 0, sms = 148;
    cudaGetDevice(&dev);
    cudaDeviceGetAttribute(&sms, cudaDevAttrMultiProcessorCount, dev);
    int grid = (nchunks + NW - 1) / NW;
    if (grid > sms) grid = sms;

    cudaFuncSetAttribute(lnn_mma, cudaFuncAttributeMaxDynamicSharedMemorySize,
                         SMEM_BYTES);
    lnn_mma<<<grid, TPB, SMEM_BYTES>>>((const float2*)x, W0, b0, W1, b1,
                                       W2, b2, W3, (float2*)d_out, B, nchunks);
}

// round 9
// speedup vs baseline: 1.9582x; 1.2249x over previous
#include <cuda_runtime.h>
#include <cuda_fp16.h>

typedef unsigned int u32;

#define TPB 384
#define NW  12   // warps per CTA

// SMEM: B-fragment bank 32KB | consts 2KB | per-warp stash (h0,h1,hd1) 144KB
#define CONST_OFF 32768
#define STASH_OFF (32768 + 2048)
#define SMEM_BYTES (STASH_OFF + NW * 32 * 96 * 4)   // 182272

__device__ __forceinline__ float ftanh(float x) {
    float e; asm("ex2.approx.f32 %0, %1;" : "=f"(e) : "f"(x * 2.8853900817779268f));
    float r; asm("rcp.approx.f32 %0, %1;" : "=f"(r) : "f"(e + 1.0f));
    return fmaf(-2.0f, r, 1.0f);
}

// split (a,b) -> packed fp16x2 hi + residual lo (value-stream digit split)
__device__ __forceinline__ void split2h(float a, float b, u32 &hi, u32 &lo) {
    __half2 h2 = __floats2half2_rn(a, b);
    hi = *reinterpret_cast<u32*>(&h2);
    float2 f = __half22float2(h2);
    __half2 l2 = __floats2half2_rn(a - f.x, b - f.y);
    lo = *reinterpret_cast<u32*>(&l2);
}
// single-digit pack (tangent stream)
__device__ __forceinline__ u32 pack2h(float a, float b) {
    __half2 h2 = __floats2half2_rn(a, b);
    return *reinterpret_cast<u32*>(&h2);
}

__device__ __forceinline__ void mma16816(float* d, const u32* a, u32 b0, u32 b1) {
    asm volatile(
        "mma.sync.aligned.m16n8k16.row.col.f32.f16.f16.f32 "
        "{%0,%1,%2,%3},{%4,%5,%6,%7},{%8,%9},{%0,%1,%2,%3};"
        : "+f"(d[0]), "+f"(d[1]), "+f"(d[2]), "+f"(d[3])
        : "r"(a[0]), "r"(a[1]), "r"(a[2]), "r"(a[3]), "r"(b0), "r"(b1));
}

// One GEMM stage: value = (Ah + Al) x Bh (2 MMAs), tangent = Th x Bh (1 MMA).
#define RUN_STAGE(S) do {                                                     \
    _Pragma("unroll")                                                         \
    for (int nt = 0; nt < 8; nt++) {                                          \
        _Pragma("unroll")                                                     \
        for (int j = 0; j < 4; j++) { zacc[nt][j] = 0.f; dacc[nt][j] = 0.f; } \
    }                                                                         \
    _Pragma("unroll")                                                         \
    for (int kt = 0; kt < 4; kt++) {                                          \
        _Pragma("unroll")                                                     \
        for (int nt = 0; nt < 8; nt++) {                                      \
            uint2 bf = bfr[(((S) * 4 + kt) * 8 + nt) * 32 + lane];            \
            mma16816(zacc[nt], Ah[kt], bf.x, bf.y);                           \
            mma16816(dacc[nt], Th[kt], bf.x, bf.y);                           \
            mma16816(zacc[nt], Al[kt], bf.x, bf.y);                           \
        }                                                                     \
    }                                                                         \
} while (0)

// D (m16n8) ntiles (2kt,2kt+1) == A (m16k16) ktile kt, reg-for-reg.
#define PACK_AFRAGS() do {                                                    \
    _Pragma("unroll")                                                         \
    for (int kt = 0; kt < 4; kt++) {                                          \
        split2h(zacc[2*kt][0],   zacc[2*kt][1],   Ah[kt][0], Al[kt][0]);      \
        split2h(zacc[2*kt][2],   zacc[2*kt][3],   Ah[kt][1], Al[kt][1]);      \
        split2h(zacc[2*kt+1][0], zacc[2*kt+1][1], Ah[kt][2], Al[kt][2]);      \
        split2h(zacc[2*kt+1][2], zacc[2*kt+1][3], Ah[kt][3], Al[kt][3]);      \
        Th[kt][0] = pack2h(dacc[2*kt][0],   dacc[2*kt][1]);                   \
        Th[kt][1] = pack2h(dacc[2*kt][2],   dacc[2*kt][3]);                   \
        Th[kt][2] = pack2h(dacc[2*kt+1][0], dacc[2*kt+1][1]);                 \
        Th[kt][3] = pack2h(dacc[2*kt+1][2], dacc[2*kt+1][3]);                 \
    }                                                                         \
} while (0)

__global__ void __launch_bounds__(TPB, 1)
lnn_mma(const float2* __restrict__ X,
        const float* __restrict__ W0, const float* __restrict__ b0,
        const float* __restrict__ W1, const float* __restrict__ b1,
        const float* __restrict__ W2, const float* __restrict__ b2,
        const float* __restrict__ W3,
        float2* __restrict__ out, int B, int nchunks)
{
    extern __shared__ __align__(16) char sm[];
    uint2* bfr = (uint2*)sm;
    float* cs = (float*)(sm + CONST_OFF);
    float* w00f = cs;       float* w01f = cs + 64;
    float* b0f  = cs + 128; float* b1f  = cs + 192;
    float* b2f  = cs + 256; float* w3f  = cs + 320;
    float* stash = (float*)(sm + STASH_OFF);

    const int t = threadIdx.x;
    if (t < 64) {
        w00f[t] = W0[t];     w01f[t] = W0[64 + t];
        b0f[t]  = b0[t];     b1f[t]  = b1[t];
        b2f[t]  = b2[t];     w3f[t]  = W3[t];
    }
    // pre-pack weight B-fragments (single fp16):
    // s0: W1 (F1), s1: W2 (F2), s2: W2^T (B1), s3: W1^T (B0)
    for (int i = t; i < 4096; i += TPB) {
        int ln = i & 31, nt = (i >> 5) & 7, kt = (i >> 8) & 3, s = i >> 10;
        int k0 = kt * 16 + (ln & 3) * 2;
        int n  = nt * 8 + (ln >> 2);
        float v0, v1, v2, v3;
        if (s == 0) {
            v0 = W1[k0*64+n]; v1 = W1[(k0+1)*64+n];
            v2 = W1[(k0+8)*64+n]; v3 = W1[(k0+9)*64+n];
        } else if (s == 1) {
            v0 = W2[k0*64+n]; v1 = W2[(k0+1)*64+n];
            v2 = W2[(k0+8)*64+n]; v3 = W2[(k0+9)*64+n];
        } else if (s == 2) {
            v0 = W2[n*64+k0]; v1 = W2[n*64+k0+1];
            v2 = W2[n*64+k0+8]; v3 = W2[n*64+k0+9];
        } else {
            v0 = W1[n*64+k0]; v1 = W1[n*64+k0+1];
            v2 = W1[n*64+k0+8]; v3 = W1[n*64+k0+9];
        }
        bfr[i] = make_uint2(pack2h(v0, v1), pack2h(v2, v3));
    }
    __syncthreads();

    const int lane = t & 31, warp = t >> 5;
    const int qr = lane >> 2;          // row within 8-row group
    const int qc = (lane & 3) * 2;     // col pair base
    // lane-private stash, stride 32: slots 0-31 h0, 32-63 h1, 64-95 hd1
    float* st = stash + warp * (96 * 32) + lane;

    for (int chunk = blockIdx.x * NW + warp; chunk < nchunks;
         chunk += gridDim.x * NW) {
        const int r0 = chunk * 16 + qr, r1 = r0 + 8;
        float2 x0 = (r0 < B) ? X[r0] : make_float2(0.f, 0.f);
        float2 x1 = (r1 < B) ? X[r1] : make_float2(0.f, 0.f);
        const float q0 = x0.x, v0 = x0.y, q1 = x1.x, v1 = x1.y;

        u32 Ah[4][4], Al[4][4], Th[4][4];

        // ===== F0: h0 (value) and hd0 (tangent) as A fragments; stash h0 =====
#pragma unroll
        for (int kt = 0; kt < 4; kt++) {
#pragma unroll
            for (int hh = 0; hh < 2; hh++) {
                int k = kt * 16 + hh * 8 + qc;
                int sb = (kt * 2 + hh) * 4;      // stash slot base
                float wa = w00f[k], wb = w00f[k+1];
                float wc = w01f[k], wd = w01f[k+1];
                float ba = b0f[k],  bb = b0f[k+1];
                float z00 = fmaf(q0, wa, fmaf(v0, wc, ba));
                float z01 = fmaf(q0, wb, fmaf(v0, wd, bb));
                float z10 = fmaf(q1, wa, fmaf(v1, wc, ba));
                float z11 = fmaf(q1, wb, fmaf(v1, wd, bb));
                float h00 = ftanh(z00), h01 = ftanh(z01);
                float h10 = ftanh(z10), h11 = ftanh(z11);
                st[(sb + 0) * 32] = h00;   // e=0,row0
                st[(sb + 1) * 32] = h10;   // e=0,row1
                st[(sb + 2) * 32] = h01;   // e=1,row0
                st[(sb + 3) * 32] = h11;   // e=1,row1
                float d00 = fmaf(-h00, h00, 1.f) * wc;
                float d01 = fmaf(-h01, h01, 1.f) * wd;
                float d10 = fmaf(-h10, h10, 1.f) * wc;
                float d11 = fmaf(-h11, h11, 1.f) * wd;
                split2h(h00, h01, Ah[kt][hh*2],   Al[kt][hh*2]);
                split2h(h10, h11, Ah[kt][hh*2+1], Al[kt][hh*2+1]);
                Th[kt][hh*2]   = pack2h(d00, d01);
                Th[kt][hh*2+1] = pack2h(d10, d11);
            }
        }

        float zacc[8][4], dacc[8][4];
        RUN_STAGE(0);

        // ===== F1 elementwise: z1 -> h1,hd1 (stash in SMEM) =====
#pragma unroll
        for (int nt = 0; nt < 8; nt++) {
#pragma unroll
            for (int j = 0; j < 4; j++) {
                int col = nt * 8 + qc + (j & 1);
                float h = ftanh(zacc[nt][j] + b1f[col]);
                float u = fmaf(-h, h, 1.f);
                float hd = u * dacc[nt][j];
                st[(32 + nt * 4 + j) * 32] = h;
                st[(64 + nt * 4 + j) * 32] = hd;
                zacc[nt][j] = h; dacc[nt][j] = hd;
            }
        }
        PACK_AFRAGS();
        RUN_STAGE(1);

        // ===== F2 elementwise: z2 -> d2, dd2 =====
#pragma unroll
        for (int nt = 0; nt < 8; nt++) {
#pragma unroll
            for (int j = 0; j < 4; j++) {
                int col = nt * 8 + qc + (j & 1);
                float h = ftanh(zacc[nt][j] + b2f[col]);
                float u = fmaf(-h, h, 1.f);
                float hd = u * dacc[nt][j];
                float w3v = w3f[col];
                zacc[nt][j] = w3v * u;                 // d2
                dacc[nt][j] = -2.f * w3v * h * hd;     // dd2
            }
        }
        PACK_AFRAGS();
        RUN_STAGE(2);

        // ===== B1 elementwise: g1,gd1 -> d1,dd1 (stash from SMEM) =====
#pragma unroll
        for (int nt = 0; nt < 8; nt++) {
#pragma unroll
            for (int j = 0; j < 4; j++) {
                float g = zacc[nt][j], gd = dacc[nt][j];
                float h  = st[(32 + nt * 4 + j) * 32];
                float hd = st[(64 + nt * 4 + j) * 32];
                float u = fmaf(-h, h, 1.f);
                zacc[nt][j] = g * u;
                dacc[nt][j] = fmaf(gd, u, -2.f * g * h * hd);
            }
        }
        PACK_AFRAGS();
        RUN_STAGE(3);

        // ===== B0 fold: g0,gd0 + stashed h0 -> per-row partials =====
        float p00 = 0.f, p01 = 0.f, p02 = 0.f;
        float p10 = 0.f, p11 = 0.f, p12 = 0.f;
#pragma unroll
        for (int nt = 0; nt < 8; nt++) {
#pragma unroll
            for (int j = 0; j < 4; j++) {
                int k = nt * 8 + qc + (j & 1);
                int rh = j >> 1;
                float wa = w00f[k], wc = w01f[k];
                float h = st[(nt * 4 + (j & 1) * 2 + rh) * 32];
                float u = fmaf(-h, h, 1.f);
                float hd = u * wc;
                float g = zacc[nt][j], gd = dacc[nt][j];
                float d0 = g * u;
                float dd0 = fmaf(gd, u, -2.f * g * h * hd);
                if (rh) {
                    p10 = fmaf(d0, wa, p10);
                    p11 = fmaf(dd0, wa, p11);
                    p12 = fmaf(dd0, wc, p12);
                } else {
                    p00 = fmaf(d0, wa, p00);
                    p01 = fmaf(dd0, wa, p01);
                    p02 = fmaf(dd0, wc, p02);
                }
            }
        }
        // reduce across the 4 lanes of each quad (disjoint k's)
#pragma unroll
        for (int m = 1; m <= 2; m <<= 1) {
            p00 += __shfl_xor_sync(0xFFFFFFFFu, p00, m);
            p01 += __shfl_xor_sync(0xFFFFFFFFu, p01, m);
            p02 += __shfl_xor_sync(0xFFFFFFFFu, p02, m);
            p10 += __shfl_xor_sync(0xFFFFFFFFu, p10, m);
            p11 += __shfl_xor_sync(0xFFFFFFFFu, p11, m);
            p12 += __shfl_xor_sync(0xFFFFFFFFu, p12, m);
        }
        if ((lane & 3) == 0) {
            if (r0 < B) {
                float a = (p00 - p01 * v0) / (p02 + 0.1f);
                out[r0] = make_float2(v0, a);
            }
            if (r1 < B) {
                float a = (p10 - p11 * v1) / (p12 + 0.1f);
                out[r1] = make_float2(v1, a);
            }
        }
    }
}

extern "C" void kernel_launch(void* const* d_in, const int* in_sizes, int n_in,
                              void* d_out, int out_size) {
    const float* x  = (const float*)d_in[1];
    const float* W0 = (const float*)d_in[2];
    const float* b0 = (const float*)d_in[3];
    const float* W1 = (const float*)d_in[4];
    const float* b1 = (const float*)d_in[5];
    const float* W2 = (const float*)d_in[6];
    const float* b2 = (const float*)d_in[7];
    const float* W3 = (const float*)d_in[8];

    const int B = in_sizes[1] / 2;
    const int nchunks = (B + 15) / 16;

    int dev = 0, sms = 148;
    cudaGetDevice(&dev);
    cudaDeviceGetAttribute(&sms, cudaDevAttrMultiProcessorCount, dev);
    int grid = (nchunks + NW - 1) / NW;
    if (grid > sms) grid = sms;

    cudaFuncSetAttribute(lnn_mma, cudaFuncAttributeMaxDynamicSharedMemorySize,
                         SMEM_BYTES);
    lnn_mma<<<grid, TPB, SMEM_BYTES>>>((const float2*)x, W0, b0, W1, b1,
                                       W2, b2, W3, (float2*)d_out, B, nchunks);
}

// round 10
// speedup vs baseline: 2.4073x; 1.2293x over previous
#include <cuda_runtime.h>
#include <cuda_fp16.h>

typedef unsigned int u32;

#define TPB 384
#define NW  12   // warps per CTA

// SMEM: B-fragment bank 32KB | consts 2KB | per-warp stash (h0,h1,hd1) 144KB
#define CONST_OFF 32768
#define STASH_OFF (32768 + 2048)
#define SMEM_BYTES (STASH_OFF + NW * 32 * 96 * 4)   // 182272

__device__ __forceinline__ float ftanh(float x) {
    float e; asm("ex2.approx.f32 %0, %1;" : "=f"(e) : "f"(x * 2.8853900817779268f));
    float r; asm("rcp.approx.f32 %0, %1;" : "=f"(r) : "f"(e + 1.0f));
    return fmaf(-2.0f, r, 1.0f);
}

// single-digit fp16x2 pack (all streams; B-quantization dominates error)
__device__ __forceinline__ u32 pack2h(float a, float b) {
    __half2 h2 = __floats2half2_rn(a, b);
    return *reinterpret_cast<u32*>(&h2);
}

__device__ __forceinline__ void mma16816(float* d, const u32* a, u32 b0, u32 b1) {
    asm volatile(
        "mma.sync.aligned.m16n8k16.row.col.f32.f16.f16.f32 "
        "{%0,%1,%2,%3},{%4,%5,%6,%7},{%8,%9},{%0,%1,%2,%3};"
        : "+f"(d[0]), "+f"(d[1]), "+f"(d[2]), "+f"(d[3])
        : "r"(a[0]), "r"(a[1]), "r"(a[2]), "r"(a[3]), "r"(b0), "r"(b1));
}

// One GEMM stage: value = Ah x Bh, tangent = Th x Bh (2 MMAs per kt,nt).
#define RUN_STAGE(S) do {                                                     \
    _Pragma("unroll")                                                         \
    for (int nt = 0; nt < 8; nt++) {                                          \
        _Pragma("unroll")                                                     \
        for (int j = 0; j < 4; j++) { zacc[nt][j] = 0.f; dacc[nt][j] = 0.f; } \
    }                                                                         \
    _Pragma("unroll")                                                         \
    for (int kt = 0; kt < 4; kt++) {                                          \
        _Pragma("unroll")                                                     \
        for (int nt = 0; nt < 8; nt++) {                                      \
            uint2 bf = bfr[(((S) * 4 + kt) * 8 + nt) * 32 + lane];            \
            mma16816(zacc[nt], Ah[kt], bf.x, bf.y);                           \
            mma16816(dacc[nt], Th[kt], bf.x, bf.y);                           \
        }                                                                     \
    }                                                                         \
} while (0)

// D (m16n8) ntiles (2kt,2kt+1) == A (m16k16) ktile kt, reg-for-reg.
#define PACK_AFRAGS() do {                                                    \
    _Pragma("unroll")                                                         \
    for (int kt = 0; kt < 4; kt++) {                                          \
        Ah[kt][0] = pack2h(zacc[2*kt][0],   zacc[2*kt][1]);                   \
        Ah[kt][1] = pack2h(zacc[2*kt][2],   zacc[2*kt][3]);                   \
        Ah[kt][2] = pack2h(zacc[2*kt+1][0], zacc[2*kt+1][1]);                 \
        Ah[kt][3] = pack2h(zacc[2*kt+1][2], zacc[2*kt+1][3]);                 \
        Th[kt][0] = pack2h(dacc[2*kt][0],   dacc[2*kt][1]);                   \
        Th[kt][1] = pack2h(dacc[2*kt][2],   dacc[2*kt][3]);                   \
        Th[kt][2] = pack2h(dacc[2*kt+1][0], dacc[2*kt+1][1]);                 \
        Th[kt][3] = pack2h(dacc[2*kt+1][2], dacc[2*kt+1][3]);                 \
    }                                                                         \
} while (0)

__global__ void __launch_bounds__(TPB, 1)
lnn_mma(const float2* __restrict__ X,
        const float* __restrict__ W0, const float* __restrict__ b0,
        const float* __restrict__ W1, const float* __restrict__ b1,
        const float* __restrict__ W2, const float* __restrict__ b2,
        const float* __restrict__ W3,
        float2* __restrict__ out, int B, int nchunks)
{
    extern __shared__ __align__(16) char sm[];
    uint2* bfr = (uint2*)sm;
    float* cs = (float*)(sm + CONST_OFF);
    float* w00f = cs;       float* w01f = cs + 64;
    float* b0f  = cs + 128; float* b1f  = cs + 192;
    float* b2f  = cs + 256; float* w3f  = cs + 320;
    float* stash = (float*)(sm + STASH_OFF);

    const int t = threadIdx.x;
    if (t < 64) {
        w00f[t] = W0[t];     w01f[t] = W0[64 + t];
        b0f[t]  = b0[t];     b1f[t]  = b1[t];
        b2f[t]  = b2[t];     w3f[t]  = W3[t];
    }
    // pre-pack weight B-fragments (single fp16):
    // s0: W1 (F1), s1: W2 (F2), s2: W2^T (B1), s3: W1^T (B0)
    for (int i = t; i < 4096; i += TPB) {
        int ln = i & 31, nt = (i >> 5) & 7, kt = (i >> 8) & 3, s = i >> 10;
        int k0 = kt * 16 + (ln & 3) * 2;
        int n  = nt * 8 + (ln >> 2);
        float v0, v1, v2, v3;
        if (s == 0) {
            v0 = W1[k0*64+n]; v1 = W1[(k0+1)*64+n];
            v2 = W1[(k0+8)*64+n]; v3 = W1[(k0+9)*64+n];
        } else if (s == 1) {
            v0 = W2[k0*64+n]; v1 = W2[(k0+1)*64+n];
            v2 = W2[(k0+8)*64+n]; v3 = W2[(k0+9)*64+n];
        } else if (s == 2) {
            v0 = W2[n*64+k0]; v1 = W2[n*64+k0+1];
            v2 = W2[n*64+k0+8]; v3 = W2[n*64+k0+9];
        } else {
            v0 = W1[n*64+k0]; v1 = W1[n*64+k0+1];
            v2 = W1[n*64+k0+8]; v3 = W1[n*64+k0+9];
        }
        bfr[i] = make_uint2(pack2h(v0, v1), pack2h(v2, v3));
    }
    __syncthreads();

    const int lane = t & 31, warp = t >> 5;
    const int qr = lane >> 2;          // row within 8-row group
    const int qc = (lane & 3) * 2;     // col pair base
    // lane-private stash, stride 32: slots 0-31 h0, 32-63 h1, 64-95 hd1
    float* st = stash + warp * (96 * 32) + lane;

    for (int chunk = blockIdx.x * NW + warp; chunk < nchunks;
         chunk += gridDim.x * NW) {
        const int r0 = chunk * 16 + qr, r1 = r0 + 8;
        float2 x0 = (r0 < B) ? X[r0] : make_float2(0.f, 0.f);
        float2 x1 = (r1 < B) ? X[r1] : make_float2(0.f, 0.f);
        const float q0 = x0.x, v0 = x0.y, q1 = x1.x, v1 = x1.y;

        u32 Ah[4][4], Th[4][4];

        // ===== F0: h0 (value) and hd0 (tangent) as A fragments; stash h0 =====
#pragma unroll
        for (int kt = 0; kt < 4; kt++) {
#pragma unroll
            for (int hh = 0; hh < 2; hh++) {
                int k = kt * 16 + hh * 8 + qc;
                int sb = (kt * 2 + hh) * 4;      // stash slot base
                float wa = w00f[k], wb = w00f[k+1];
                float wc = w01f[k], wd = w01f[k+1];
                float ba = b0f[k],  bb = b0f[k+1];
                float z00 = fmaf(q0, wa, fmaf(v0, wc, ba));
                float z01 = fmaf(q0, wb, fmaf(v0, wd, bb));
                float z10 = fmaf(q1, wa, fmaf(v1, wc, ba));
                float z11 = fmaf(q1, wb, fmaf(v1, wd, bb));
                float h00 = ftanh(z00), h01 = ftanh(z01);
                float h10 = ftanh(z10), h11 = ftanh(z11);
                st[(sb + 0) * 32] = h00;   // e=0,row0
                st[(sb + 1) * 32] = h10;   // e=0,row1
                st[(sb + 2) * 32] = h01;   // e=1,row0
                st[(sb + 3) * 32] = h11;   // e=1,row1
                float d00 = fmaf(-h00, h00, 1.f) * wc;
                float d01 = fmaf(-h01, h01, 1.f) * wd;
                float d10 = fmaf(-h10, h10, 1.f) * wc;
                float d11 = fmaf(-h11, h11, 1.f) * wd;
                Ah[kt][hh*2]   = pack2h(h00, h01);
                Ah[kt][hh*2+1] = pack2h(h10, h11);
                Th[kt][hh*2]   = pack2h(d00, d01);
                Th[kt][hh*2+1] = pack2h(d10, d11);
            }
        }

        float zacc[8][4], dacc[8][4];
        RUN_STAGE(0);

        // ===== F1 elementwise: z1 -> h1,hd1 (stash in SMEM) =====
#pragma unroll
        for (int nt = 0; nt < 8; nt++) {
#pragma unroll
            for (int j = 0; j < 4; j++) {
                int col = nt * 8 + qc + (j & 1);
                float h = ftanh(zacc[nt][j] + b1f[col]);
                float u = fmaf(-h, h, 1.f);
                float hd = u * dacc[nt][j];
                st[(32 + nt * 4 + j) * 32] = h;
                st[(64 + nt * 4 + j) * 32] = hd;
                zacc[nt][j] = h; dacc[nt][j] = hd;
            }
        }
        PACK_AFRAGS();
        RUN_STAGE(1);

        // ===== F2 elementwise: z2 -> d2, dd2 =====
#pragma unroll
        for (int nt = 0; nt < 8; nt++) {
#pragma unroll
            for (int j = 0; j < 4; j++) {
                int col = nt * 8 + qc + (j & 1);
                float h = ftanh(zacc[nt][j] + b2f[col]);
                float u = fmaf(-h, h, 1.f);
                float hd = u * dacc[nt][j];
                float w3v = w3f[col];
                zacc[nt][j] = w3v * u;                 // d2
                dacc[nt][j] = -2.f * w3v * h * hd;     // dd2
            }
        }
        PACK_AFRAGS();
        RUN_STAGE(2);

        // ===== B1 elementwise: g1,gd1 -> d1,dd1 (stash from SMEM) =====
#pragma unroll
        for (int nt = 0; nt < 8; nt++) {
#pragma unroll
            for (int j = 0; j < 4; j++) {
                float g = zacc[nt][j], gd = dacc[nt][j];
                float h  = st[(32 + nt * 4 + j) * 32];
                float hd = st[(64 + nt * 4 + j) * 32];
                float u = fmaf(-h, h, 1.f);
                zacc[nt][j] = g * u;
                dacc[nt][j] = fmaf(gd, u, -2.f * g * h * hd);
            }
        }
        PACK_AFRAGS();
        RUN_STAGE(3);

        // ===== B0 fold: g0,gd0 + stashed h0 -> per-row partials =====
        float p00 = 0.f, p01 = 0.f, p02 = 0.f;
        float p10 = 0.f, p11 = 0.f, p12 = 0.f;
#pragma unroll
        for (int nt = 0; nt < 8; nt++) {
#pragma unroll
            for (int j = 0; j < 4; j++) {
                int k = nt * 8 + qc + (j & 1);
                int rh = j >> 1;
                float wa = w00f[k], wc = w01f[k];
                float h = st[(nt * 4 + (j & 1) * 2 + rh) * 32];
                float u = fmaf(-h, h, 1.f);
                float hd = u * wc;
                float g = zacc[nt][j], gd = dacc[nt][j];
                float d0 = g * u;
                float dd0 = fmaf(gd, u, -2.f * g * h * hd);
                if (rh) {
                    p10 = fmaf(d0, wa, p10);
                    p11 = fmaf(dd0, wa, p11);
                    p12 = fmaf(dd0, wc, p12);
                } else {
                    p00 = fmaf(d0, wa, p00);
                    p01 = fmaf(dd0, wa, p01);
                    p02 = fmaf(dd0, wc, p02);
                }
            }
        }
        // reduce across the 4 lanes of each quad (disjoint k's)
#pragma unroll
        for (int m = 1; m <= 2; m <<= 1) {
            p00 += __shfl_xor_sync(0xFFFFFFFFu, p00, m);
            p01 += __shfl_xor_sync(0xFFFFFFFFu, p01, m);
            p02 += __shfl_xor_sync(0xFFFFFFFFu, p02, m);
            p10 += __shfl_xor_sync(0xFFFFFFFFu, p10, m);
            p11 += __shfl_xor_sync(0xFFFFFFFFu, p11, m);
            p12 += __shfl_xor_sync(0xFFFFFFFFu, p12, m);
        }
        if ((lane & 3) == 0) {
            if (r0 < B) {
                float a = (p00 - p01 * v0) / (p02 + 0.1f);
                out[r0] = make_float2(v0, a);
            }
            if (r1 < B) {
                float a = (p10 - p11 * v1) / (p12 + 0.1f);
                out[r1] = make_float2(v1, a);
            }
        }
    }
}

extern "C" void kernel_launch(void* const* d_in, const int* in_sizes, int n_in,
                              void* d_out, int out_size) {
    const float* x  = (const float*)d_in[1];
    const float* W0 = (const float*)d_in[2];
    const float* b0 = (const float*)d_in[3];
    const float* W1 = (const float*)d_in[4];
    const float* b1 = (const float*)d_in[5];
    const float* W2 = (const float*)d_in[6];
    const float* b2 = (const float*)d_in[7];
    const float* W3 = (const float*)d_in[8];

    const int B = in_sizes[1] / 2;
    const int nchunks = (B + 15) / 16;

    int dev = 0, sms = 148;
    cudaGetDevice(&dev);
    cudaDeviceGetAttribute(&sms, cudaDevAttrMultiProcessorCount, dev);
    int grid = (nchunks + NW - 1) / NW;
    if (grid > sms) grid = sms;

    cudaFuncSetAttribute(lnn_mma, cudaFuncAttributeMaxDynamicSharedMemorySize,
                         SMEM_BYTES);
    lnn_mma<<<grid, TPB, SMEM_BYTES>>>((const float2*)x, W0, b0, W1, b1,
                                       W2, b2, W3, (float2*)d_out, B, nchunks);
}

// round 11
// speedup vs baseline: 2.6493x; 1.1005x over previous
#include <cuda_runtime.h>
#include <cuda_fp16.h>

typedef unsigned int u32;

#define TPB 384
#define NW  12   // warps per CTA

// SMEM: B-fragment bank 32KB | consts 2KB | per-warp stash (h0,h1/hd1 pairs) 144KB
#define CONST_OFF 32768
#define STASH_OFF (32768 + 2048)
#define SMEM_BYTES (STASH_OFF + NW * 32 * 96 * 4)   // 182272

__device__ __forceinline__ float ftanh(float x) {
    float e; asm("ex2.approx.f32 %0, %1;" : "=f"(e) : "f"(x * 2.8853900817779268f));
    float r; asm("rcp.approx.f32 %0, %1;" : "=f"(r) : "f"(e + 1.0f));
    return fmaf(-2.0f, r, 1.0f);
}

// single-digit fp16x2 pack (all streams; B-quantization dominates error)
__device__ __forceinline__ u32 pack2h(float a, float b) {
    __half2 h2 = __floats2half2_rn(a, b);
    return *reinterpret_cast<u32*>(&h2);
}

// accumulate form: D = A*B + D
__device__ __forceinline__ void mma16816(float* d, const u32* a, u32 b0, u32 b1) {
    asm volatile(
        "mma.sync.aligned.m16n8k16.row.col.f32.f16.f16.f32 "
        "{%0,%1,%2,%3},{%4,%5,%6,%7},{%8,%9},{%0,%1,%2,%3};"
        : "+f"(d[0]), "+f"(d[1]), "+f"(d[2]), "+f"(d[3])
        : "r"(a[0]), "r"(a[1]), "r"(a[2]), "r"(a[3]), "r"(b0), "r"(b1));
}
// zero-C form: D = A*B + 0  (no accumulator zero-init needed)
__device__ __forceinline__ void mma16816_z(float* d, const u32* a, u32 b0, u32 b1) {
    asm volatile(
        "mma.sync.aligned.m16n8k16.row.col.f32.f16.f16.f32 "
        "{%0,%1,%2,%3},{%4,%5,%6,%7},{%8,%9},{%10,%11,%12,%13};"
        : "=f"(d[0]), "=f"(d[1]), "=f"(d[2]), "=f"(d[3])
        : "r"(a[0]), "r"(a[1]), "r"(a[2]), "r"(a[3]), "r"(b0), "r"(b1),
          "f"(0.0f), "f"(0.0f), "f"(0.0f), "f"(0.0f));
}

// One GEMM stage: value = Ah x Bh, tangent = Th x Bh. kt=0 writes fresh (zero-C).
#define RUN_STAGE(S) do {                                                     \
    _Pragma("unroll")                                                         \
    for (int kt = 0; kt < 4; kt++) {                                          \
        _Pragma("unroll")                                                     \
        for (int nt = 0; nt < 8; nt++) {                                      \
            uint2 bf = bfr[(((S) * 4 + kt) * 8 + nt) * 32 + lane];            \
            if (kt == 0) {                                                    \
                mma16816_z(zacc[nt], Ah[kt], bf.x, bf.y);                     \
                mma16816_z(dacc[nt], Th[kt], bf.x, bf.y);                     \
            } else {                                                          \
                mma16816(zacc[nt], Ah[kt], bf.x, bf.y);                       \
                mma16816(dacc[nt], Th[kt], bf.x, bf.y);                       \
            }                                                                 \
        }                                                                     \
    }                                                                         \
} while (0)

// D (m16n8) ntiles (2kt,2kt+1) == A (m16k16) ktile kt, reg-for-reg.
#define PACK_AFRAGS() do {                                                    \
    _Pragma("unroll")                                                         \
    for (int kt = 0; kt < 4; kt++) {                                          \
        Ah[kt][0] = pack2h(zacc[2*kt][0],   zacc[2*kt][1]);                   \
        Ah[kt][1] = pack2h(zacc[2*kt][2],   zacc[2*kt][3]);                   \
        Ah[kt][2] = pack2h(zacc[2*kt+1][0], zacc[2*kt+1][1]);                 \
        Ah[kt][3] = pack2h(zacc[2*kt+1][2], zacc[2*kt+1][3]);                 \
        Th[kt][0] = pack2h(dacc[2*kt][0],   dacc[2*kt][1]);                   \
        Th[kt][1] = pack2h(dacc[2*kt][2],   dacc[2*kt][3]);                   \
        Th[kt][2] = pack2h(dacc[2*kt+1][0], dacc[2*kt+1][1]);                 \
        Th[kt][3] = pack2h(dacc[2*kt+1][2], dacc[2*kt+1][3]);                 \
    }                                                                         \
} while (0)

__global__ void __launch_bounds__(TPB, 1)
lnn_mma(const float2* __restrict__ X,
        const float* __restrict__ W0, const float* __restrict__ b0,
        const float* __restrict__ W1, const float* __restrict__ b1,
        const float* __restrict__ W2, const float* __restrict__ b2,
        const float* __restrict__ W3,
        float2* __restrict__ out, int B, int nchunks)
{
    extern __shared__ __align__(16) char sm[];
    uint2* bfr = (uint2*)sm;
    float* cs = (float*)(sm + CONST_OFF);
    float* w00f = cs;       float* w01f = cs + 64;
    float* b0f  = cs + 128; float* b1f  = cs + 192;
    float* b2f  = cs + 256; float* w3f  = cs + 320;
    float* stash = (float*)(sm + STASH_OFF);

    const int t = threadIdx.x;
    if (t < 64) {
        w00f[t] = W0[t];     w01f[t] = W0[64 + t];
        b0f[t]  = b0[t];     b1f[t]  = b1[t];
        b2f[t]  = b2[t];     w3f[t]  = W3[t];
    }
    // pre-pack weight B-fragments (single fp16):
    // s0: W1 (F1), s1: W2 (F2), s2: W2^T (B1), s3: W1^T (B0)
    for (int i = t; i < 4096; i += TPB) {
        int ln = i & 31, nt = (i >> 5) & 7, kt = (i >> 8) & 3, s = i >> 10;
        int k0 = kt * 16 + (ln & 3) * 2;
        int n  = nt * 8 + (ln >> 2);
        float v0, v1, v2, v3;
        if (s == 0) {
            v0 = W1[k0*64+n]; v1 = W1[(k0+1)*64+n];
            v2 = W1[(k0+8)*64+n]; v3 = W1[(k0+9)*64+n];
        } else if (s == 1) {
            v0 = W2[k0*64+n]; v1 = W2[(k0+1)*64+n];
            v2 = W2[(k0+8)*64+n]; v3 = W2[(k0+9)*64+n];
        } else if (s == 2) {
            v0 = W2[n*64+k0]; v1 = W2[n*64+k0+1];
            v2 = W2[n*64+k0+8]; v3 = W2[n*64+k0+9];
        } else {
            v0 = W1[n*64+k0]; v1 = W1[n*64+k0+1];
            v2 = W1[n*64+k0+8]; v3 = W1[n*64+k0+9];
        }
        bfr[i] = make_uint2(pack2h(v0, v1), pack2h(v2, v3));
    }
    __syncthreads();

    const int lane = t & 31, warp = t >> 5;
    const int qr = lane >> 2;          // row within 8-row group
    const int qc = (lane & 3) * 2;     // col pair base
    // per-warp lane-interleaved float2 stash (48 float2/lane):
    //   pair idx 0..15 : h0 pairs (h[e][row0], h[e][row1])
    //   pair idx 16..47: (h1, hd1) pairs
    float2* sp = (float2*)(stash + warp * (96 * 32)) + lane;

    for (int chunk = blockIdx.x * NW + warp; chunk < nchunks;
         chunk += gridDim.x * NW) {
        const int r0 = chunk * 16 + qr, r1 = r0 + 8;
        float2 x0 = (r0 < B) ? X[r0] : make_float2(0.f, 0.f);
        float2 x1 = (r1 < B) ? X[r1] : make_float2(0.f, 0.f);
        const float q0 = x0.x, v0 = x0.y, q1 = x1.x, v1 = x1.y;

        u32 Ah[4][4], Th[4][4];

        // ===== F0: h0 (value) and hd0 (tangent) as A fragments; stash h0 pairs =====
#pragma unroll
        for (int kt = 0; kt < 4; kt++) {
#pragma unroll
            for (int hh = 0; hh < 2; hh++) {
                int k = kt * 16 + hh * 8 + qc;
                int pb = (kt * 2 + hh) * 2;      // h0 pair base
                float wa = w00f[k], wb = w00f[k+1];
                float wc = w01f[k], wd = w01f[k+1];
                float ba = b0f[k],  bb = b0f[k+1];
                float z00 = fmaf(q0, wa, fmaf(v0, wc, ba));
                float z01 = fmaf(q0, wb, fmaf(v0, wd, bb));
                float z10 = fmaf(q1, wa, fmaf(v1, wc, ba));
                float z11 = fmaf(q1, wb, fmaf(v1, wd, bb));
                float h00 = ftanh(z00), h01 = ftanh(z01);
                float h10 = ftanh(z10), h11 = ftanh(z11);
                sp[(pb + 0) * 32] = make_float2(h00, h10);  // e=0: (row0,row1)
                sp[(pb + 1) * 32] = make_float2(h01, h11);  // e=1: (row0,row1)
                float d00 = fmaf(-h00, h00, 1.f) * wc;
                float d01 = fmaf(-h01, h01, 1.f) * wd;
                float d10 = fmaf(-h10, h10, 1.f) * wc;
                float d11 = fmaf(-h11, h11, 1.f) * wd;
                Ah[kt][hh*2]   = pack2h(h00, h01);
                Ah[kt][hh*2+1] = pack2h(h10, h11);
                Th[kt][hh*2]   = pack2h(d00, d01);
                Th[kt][hh*2+1] = pack2h(d10, d11);
            }
        }

        float zacc[8][4], dacc[8][4];
        RUN_STAGE(0);

        // ===== F1 elementwise: z1 -> h1,hd1 (paired stash) =====
#pragma unroll
        for (int nt = 0; nt < 8; nt++) {
#pragma unroll
            for (int j = 0; j < 4; j++) {
                int col = nt * 8 + qc + (j & 1);
                float h = ftanh(zacc[nt][j] + b1f[col]);
                float u = fmaf(-h, h, 1.f);
                float hd = u * dacc[nt][j];
                sp[(16 + nt * 4 + j) * 32] = make_float2(h, hd);
                zacc[nt][j] = h; dacc[nt][j] = hd;
            }
        }
        PACK_AFRAGS();
        RUN_STAGE(1);

        // ===== F2 elementwise: z2 -> d2, dd2 =====
#pragma unroll
        for (int nt = 0; nt < 8; nt++) {
#pragma unroll
            for (int j = 0; j < 4; j++) {
                int col = nt * 8 + qc + (j & 1);
                float h = ftanh(zacc[nt][j] + b2f[col]);
                float u = fmaf(-h, h, 1.f);
                float hd = u * dacc[nt][j];
                float w3v = w3f[col];
                zacc[nt][j] = w3v * u;                 // d2
                dacc[nt][j] = -2.f * w3v * h * hd;     // dd2
            }
        }
        PACK_AFRAGS();
        RUN_STAGE(2);

        // ===== B1 elementwise: g1,gd1 -> d1,dd1 (paired stash load) =====
#pragma unroll
        for (int nt = 0; nt < 8; nt++) {
#pragma unroll
            for (int j = 0; j < 4; j++) {
                float g = zacc[nt][j], gd = dacc[nt][j];
                float2 hp = sp[(16 + nt * 4 + j) * 32];
                float h = hp.x, hd = hp.y;
                float u = fmaf(-h, h, 1.f);
                zacc[nt][j] = g * u;
                dacc[nt][j] = fmaf(gd, u, -2.f * g * h * hd);
            }
        }
        PACK_AFRAGS();
        RUN_STAGE(3);

        // ===== B0 fold: g0,gd0 + stashed h0 pairs -> per-row partials =====
        float p00 = 0.f, p01 = 0.f, p02 = 0.f;
        float p10 = 0.f, p11 = 0.f, p12 = 0.f;
#pragma unroll
        for (int nt = 0; nt < 8; nt++) {
#pragma unroll
            for (int e = 0; e < 2; e++) {
                int k = nt * 8 + qc + e;
                float wa = w00f[k], wc = w01f[k];
                float2 hp = sp[(nt * 2 + e) * 32];
                {   // row0 (j = e)
                    float h = hp.x;
                    float u = fmaf(-h, h, 1.f);
                    float hd = u * wc;
                    float g = zacc[nt][e], gd = dacc[nt][e];
                    float d0 = g * u;
                    float dd0 = fmaf(gd, u, -2.f * g * h * hd);
                    p00 = fmaf(d0, wa, p00);
                    p01 = fmaf(dd0, wa, p01);
                    p02 = fmaf(dd0, wc, p02);
                }
                {   // row1 (j = e+2)
                    float h = hp.y;
                    float u = fmaf(-h, h, 1.f);
                    float hd = u * wc;
                    float g = zacc[nt][e + 2], gd = dacc[nt][e + 2];
                    float d0 = g * u;
                    float dd0 = fmaf(gd, u, -2.f * g * h * hd);
                    p10 = fmaf(d0, wa, p10);
                    p11 = fmaf(dd0, wa, p11);
                    p12 = fmaf(dd0, wc, p12);
                }
            }
        }
        // reduce across the 4 lanes of each quad (disjoint k's)
#pragma unroll
        for (int m = 1; m <= 2; m <<= 1) {
            p00 += __shfl_xor_sync(0xFFFFFFFFu, p00, m);
            p01 += __shfl_xor_sync(0xFFFFFFFFu, p01, m);
            p02 += __shfl_xor_sync(0xFFFFFFFFu, p02, m);
            p10 += __shfl_xor_sync(0xFFFFFFFFu, p10, m);
            p11 += __shfl_xor_sync(0xFFFFFFFFu, p11, m);
            p12 += __shfl_xor_sync(0xFFFFFFFFu, p12, m);
        }
        if ((lane & 3) == 0) {
            if (r0 < B) {
                float a = (p00 - p01 * v0) / (p02 + 0.1f);
                out[r0] = make_float2(v0, a);
            }
            if (r1 < B) {
                float a = (p10 - p11 * v1) / (p12 + 0.1f);
                out[r1] = make_float2(v1, a);
            }
        }
    }
}

extern "C" void kernel_launch(void* const* d_in, const int* in_sizes, int n_in,
                              void* d_out, int out_size) {
    const float* x  = (const float*)d_in[1];
    const float* W0 = (const float*)d_in[2];
    const float* b0 = (const float*)d_in[3];
    const float* W1 = (const float*)d_in[4];
    const float* b1 = (const float*)d_in[5];
    const float* W2 = (const float*)d_in[6];
    const float* b2 = (const float*)d_in[7];
    const float* W3 = (const float*)d_in[8];

    const int B = in_sizes[1] / 2;
    const int nchunks = (B + 15) / 16;

    int dev = 0, sms = 148;
    cudaGetDevice(&dev);
    cudaDeviceGetAttribute(&sms, cudaDevAttrMultiProcessorCount, dev);
    int grid = (nchunks + NW - 1) / NW;
    if (grid > sms) grid = sms;

    cudaFuncSetAttribute(lnn_mma, cudaFuncAttributeMaxDynamicSharedMemorySize,
                         SMEM_BYTES);
    lnn_mma<<<grid, TPB, SMEM_BYTES>>>((const float2*)x, W0, b0, W1, b1,
                                       W2, b2, W3, (float2*)d_out, B, nchunks);
}

// round 12
// speedup vs baseline: 3.4888x; 1.3169x over previous
#include <cuda_runtime.h>
#include <cuda_fp16.h>

typedef unsigned int u32;

#define TPB 384
#define NW  12   // warps per CTA

// SMEM: B-fragment bank 32KB | consts 2KB | per-warp stash (h0,h1/hd1 pairs) 144KB
#define CONST_OFF 32768
#define STASH_OFF (32768 + 2048)
#define SMEM_BYTES (STASH_OFF + NW * 32 * 96 * 4)   // 182272

// hardware tanh: 1 instr, 1 MUFU (sm_75+; max abs err ~2^-10.66, same order
// as the fp16 quantization already applied to these values downstream)
__device__ __forceinline__ float ftanh(float x) {
    float r; asm("tanh.approx.f32 %0, %1;" : "=f"(r) : "f"(x));
    return r;
}

// single-digit fp16x2 pack (all streams; B-quantization dominates error)
__device__ __forceinline__ u32 pack2h(float a, float b) {
    __half2 h2 = __floats2half2_rn(a, b);
    return *reinterpret_cast<u32*>(&h2);
}

// accumulate form: D = A*B + D
__device__ __forceinline__ void mma16816(float* d, const u32* a, u32 b0, u32 b1) {
    asm volatile(
        "mma.sync.aligned.m16n8k16.row.col.f32.f16.f16.f32 "
        "{%0,%1,%2,%3},{%4,%5,%6,%7},{%8,%9},{%0,%1,%2,%3};"
        : "+f"(d[0]), "+f"(d[1]), "+f"(d[2]), "+f"(d[3])
        : "r"(a[0]), "r"(a[1]), "r"(a[2]), "r"(a[3]), "r"(b0), "r"(b1));
}
// zero-C form: D = A*B + 0  (no accumulator zero-init needed)
__device__ __forceinline__ void mma16816_z(float* d, const u32* a, u32 b0, u32 b1) {
    asm volatile(
        "mma.sync.aligned.m16n8k16.row.col.f32.f16.f16.f32 "
        "{%0,%1,%2,%3},{%4,%5,%6,%7},{%8,%9},{%10,%11,%12,%13};"
        : "=f"(d[0]), "=f"(d[1]), "=f"(d[2]), "=f"(d[3])
        : "r"(a[0]), "r"(a[1]), "r"(a[2]), "r"(a[3]), "r"(b0), "r"(b1),
          "f"(0.0f), "f"(0.0f), "f"(0.0f), "f"(0.0f));
}

// One GEMM stage: value = Ah x Bh, tangent = Th x Bh. kt=0 writes fresh (zero-C).
#define RUN_STAGE(S) do {                                                     \
    _Pragma("unroll")                                                         \
    for (int kt = 0; kt < 4; kt++) {                                          \
        _Pragma("unroll")                                                     \
        for (int nt = 0; nt < 8; nt++) {                                      \
            uint2 bf = bfr[(((S) * 4 + kt) * 8 + nt) * 32 + lane];            \
            if (kt == 0) {                                                    \
                mma16816_z(zacc[nt], Ah[kt], bf.x, bf.y);                     \
                mma16816_z(dacc[nt], Th[kt], bf.x, bf.y);                     \
            } else {                                                          \
                mma16816(zacc[nt], Ah[kt], bf.x, bf.y);                       \
                mma16816(dacc[nt], Th[kt], bf.x, bf.y);                       \
            }                                                                 \
        }                                                                     \
    }                                                                         \
} while (0)

// D (m16n8) ntiles (2kt,2kt+1) == A (m16k16) ktile kt, reg-for-reg.
#define PACK_AFRAGS() do {                                                    \
    _Pragma("unroll")                                                         \
    for (int kt = 0; kt < 4; kt++) {                                          \
        Ah[kt][0] = pack2h(zacc[2*kt][0],   zacc[2*kt][1]);                   \
        Ah[kt][1] = pack2h(zacc[2*kt][2],   zacc[2*kt][3]);                   \
        Ah[kt][2] = pack2h(zacc[2*kt+1][0], zacc[2*kt+1][1]);                 \
        Ah[kt][3] = pack2h(zacc[2*kt+1][2], zacc[2*kt+1][3]);                 \
        Th[kt][0] = pack2h(dacc[2*kt][0],   dacc[2*kt][1]);                   \
        Th[kt][1] = pack2h(dacc[2*kt][2],   dacc[2*kt][3]);                   \
        Th[kt][2] = pack2h(dacc[2*kt+1][0], dacc[2*kt+1][1]);                 \
        Th[kt][3] = pack2h(dacc[2*kt+1][2], dacc[2*kt+1][3]);                 \
    }                                                                         \
} while (0)

__global__ void __launch_bounds__(TPB, 1)
lnn_mma(const float2* __restrict__ X,
        const float* __restrict__ W0, const float* __restrict__ b0,
        const float* __restrict__ W1, const float* __restrict__ b1,
        const float* __restrict__ W2, const float* __restrict__ b2,
        const float* __restrict__ W3,
        float2* __restrict__ out, int B, int nchunks)
{
    extern __shared__ __align__(16) char sm[];
    uint2* bfr = (uint2*)sm;
    float* cs = (float*)(sm + CONST_OFF);
    float* w00f = cs;       float* w01f = cs + 64;
    float* b0f  = cs + 128; float* b1f  = cs + 192;
    float* b2f  = cs + 256; float* w3f  = cs + 320;
    float* stash = (float*)(sm + STASH_OFF);

    const int t = threadIdx.x;
    if (t < 64) {
        w00f[t] = W0[t];     w01f[t] = W0[64 + t];
        b0f[t]  = b0[t];     b1f[t]  = b1[t];
        b2f[t]  = b2[t];     w3f[t]  = W3[t];
    }
    // pre-pack weight B-fragments (single fp16):
    // s0: W1 (F1), s1: W2 (F2), s2: W2^T (B1), s3: W1^T (B0)
    for (int i = t; i < 4096; i += TPB) {
        int ln = i & 31, nt = (i >> 5) & 7, kt = (i >> 8) & 3, s = i >> 10;
        int k0 = kt * 16 + (ln & 3) * 2;
        int n  = nt * 8 + (ln >> 2);
        float v0, v1, v2, v3;
        if (s == 0) {
            v0 = W1[k0*64+n]; v1 = W1[(k0+1)*64+n];
            v2 = W1[(k0+8)*64+n]; v3 = W1[(k0+9)*64+n];
        } else if (s == 1) {
            v0 = W2[k0*64+n]; v1 = W2[(k0+1)*64+n];
            v2 = W2[(k0+8)*64+n]; v3 = W2[(k0+9)*64+n];
        } else if (s == 2) {
            v0 = W2[n*64+k0]; v1 = W2[n*64+k0+1];
            v2 = W2[n*64+k0+8]; v3 = W2[n*64+k0+9];
        } else {
            v0 = W1[n*64+k0]; v1 = W1[n*64+k0+1];
            v2 = W1[n*64+k0+8]; v3 = W1[n*64+k0+9];
        }
        bfr[i] = make_uint2(pack2h(v0, v1), pack2h(v2, v3));
    }
    __syncthreads();

    const int lane = t & 31, warp = t >> 5;
    const int qr = lane >> 2;          // row within 8-row group
    const int qc = (lane & 3) * 2;     // col pair base
    // per-warp lane-interleaved float2 stash (48 float2/lane):
    //   pair idx 0..15 : h0 pairs (h[e][row0], h[e][row1])
    //   pair idx 16..47: (h1, hd1) pairs
    float2* sp = (float2*)(stash + warp * (96 * 32)) + lane;

    for (int chunk = blockIdx.x * NW + warp; chunk < nchunks;
         chunk += gridDim.x * NW) {
        const int r0 = chunk * 16 + qr, r1 = r0 + 8;
        float2 x0 = (r0 < B) ? X[r0] : make_float2(0.f, 0.f);
        float2 x1 = (r1 < B) ? X[r1] : make_float2(0.f, 0.f);
        const float q0 = x0.x, v0 = x0.y, q1 = x1.x, v1 = x1.y;

        u32 Ah[4][4], Th[4][4];

        // ===== F0: h0 (value) and hd0 (tangent) as A fragments; stash h0 pairs =====
#pragma unroll
        for (int kt = 0; kt < 4; kt++) {
#pragma unroll
            for (int hh = 0; hh < 2; hh++) {
                int k = kt * 16 + hh * 8 + qc;
                int pb = (kt * 2 + hh) * 2;      // h0 pair base
                float wa = w00f[k], wb = w00f[k+1];
                float wc = w01f[k], wd = w01f[k+1];
                float ba = b0f[k],  bb = b0f[k+1];
                float z00 = fmaf(q0, wa, fmaf(v0, wc, ba));
                float z01 = fmaf(q0, wb, fmaf(v0, wd, bb));
                float z10 = fmaf(q1, wa, fmaf(v1, wc, ba));
                float z11 = fmaf(q1, wb, fmaf(v1, wd, bb));
                float h00 = ftanh(z00), h01 = ftanh(z01);
                float h10 = ftanh(z10), h11 = ftanh(z11);
                sp[(pb + 0) * 32] = make_float2(h00, h10);  // e=0: (row0,row1)
                sp[(pb + 1) * 32] = make_float2(h01, h11);  // e=1: (row0,row1)
                float d00 = fmaf(-h00, h00, 1.f) * wc;
                float d01 = fmaf(-h01, h01, 1.f) * wd;
                float d10 = fmaf(-h10, h10, 1.f) * wc;
                float d11 = fmaf(-h11, h11, 1.f) * wd;
                Ah[kt][hh*2]   = pack2h(h00, h01);
                Ah[kt][hh*2+1] = pack2h(h10, h11);
                Th[kt][hh*2]   = pack2h(d00, d01);
                Th[kt][hh*2+1] = pack2h(d10, d11);
            }
        }

        float zacc[8][4], dacc[8][4];
        RUN_STAGE(0);

        // ===== F1 elementwise: z1 -> h1,hd1 (paired stash) =====
#pragma unroll
        for (int nt = 0; nt < 8; nt++) {
#pragma unroll
            for (int j = 0; j < 4; j++) {
                int col = nt * 8 + qc + (j & 1);
                float h = ftanh(zacc[nt][j] + b1f[col]);
                float u = fmaf(-h, h, 1.f);
                float hd = u * dacc[nt][j];
                sp[(16 + nt * 4 + j) * 32] = make_float2(h, hd);
                zacc[nt][j] = h; dacc[nt][j] = hd;
            }
        }
        PACK_AFRAGS();
        RUN_STAGE(1);

        // ===== F2 elementwise: z2 -> d2, dd2 =====
#pragma unroll
        for (int nt = 0; nt < 8; nt++) {
#pragma unroll
            for (int j = 0; j < 4; j++) {
                int col = nt * 8 + qc + (j & 1);
                float h = ftanh(zacc[nt][j] + b2f[col]);
                float u = fmaf(-h, h, 1.f);
                float hd = u * dacc[nt][j];
                float w3v = w3f[col];
                zacc[nt][j] = w3v * u;                 // d2
                dacc[nt][j] = -2.f * w3v * h * hd;     // dd2
            }
        }
        PACK_AFRAGS();
        RUN_STAGE(2);

        // ===== B1 elementwise: g1,gd1 -> d1,dd1 (paired stash load) =====
#pragma unroll
        for (int nt = 0; nt < 8; nt++) {
#pragma unroll
            for (int j = 0; j < 4; j++) {
                float g = zacc[nt][j], gd = dacc[nt][j];
                float2 hp = sp[(16 + nt * 4 + j) * 32];
                float h = hp.x, hd = hp.y;
                float u = fmaf(-h, h, 1.f);
                zacc[nt][j] = g * u;
                dacc[nt][j] = fmaf(gd, u, -2.f * g * h * hd);
            }
        }
        PACK_AFRAGS();
        RUN_STAGE(3);

        // ===== B0 fold: g0,gd0 + stashed h0 pairs -> per-row partials =====
        float p00 = 0.f, p01 = 0.f, p02 = 0.f;
        float p10 = 0.f, p11 = 0.f, p12 = 0.f;
#pragma unroll
        for (int nt = 0; nt < 8; nt++) {
#pragma unroll
            for (int e = 0; e < 2; e++) {
                int k = nt * 8 + qc + e;
                float wa = w00f[k], wc = w01f[k];
                float2 hp = sp[(nt * 2 + e) * 32];
                {   // row0 (j = e)
                    float h = hp.x;
                    float u = fmaf(-h, h, 1.f);
                    float hd = u * wc;
                    float g = zacc[nt][e], gd = dacc[nt][e];
                    float d0 = g * u;
                    float dd0 = fmaf(gd, u, -2.f * g * h * hd);
                    p00 = fmaf(d0, wa, p00);
                    p01 = fmaf(dd0, wa, p01);
                    p02 = fmaf(dd0, wc, p02);
                }
                {   // row1 (j = e+2)
                    float h = hp.y;
                    float u = fmaf(-h, h, 1.f);
                    float hd = u * wc;
                    float g = zacc[nt][e + 2], gd = dacc[nt][e + 2];
                    float d0 = g * u;
                    float dd0 = fmaf(gd, u, -2.f * g * h * hd);
                    p10 = fmaf(d0, wa, p10);
                    p11 = fmaf(dd0, wa, p11);
                    p12 = fmaf(dd0, wc, p12);
                }
            }
        }
        // reduce across the 4 lanes of each quad (disjoint k's)
#pragma unroll
        for (int m = 1; m <= 2; m <<= 1) {
            p00 += __shfl_xor_sync(0xFFFFFFFFu, p00, m);
            p01 += __shfl_xor_sync(0xFFFFFFFFu, p01, m);
            p02 += __shfl_xor_sync(0xFFFFFFFFu, p02, m);
            p10 += __shfl_xor_sync(0xFFFFFFFFu, p10, m);
            p11 += __shfl_xor_sync(0xFFFFFFFFu, p11, m);
            p12 += __shfl_xor_sync(0xFFFFFFFFu, p12, m);
        }
        if ((lane & 3) == 0) {
            if (r0 < B) {
                float a = (p00 - p01 * v0) / (p02 + 0.1f);
                out[r0] = make_float2(v0, a);
            }
            if (r1 < B) {
                float a = (p10 - p11 * v1) / (p12 + 0.1f);
                out[r1] = make_float2(v1, a);
            }
        }
    }
}

extern "C" void kernel_launch(void* const* d_in, const int* in_sizes, int n_in,
                              void* d_out, int out_size) {
    const float* x  = (const float*)d_in[1];
    const float* W0 = (const float*)d_in[2];
    const float* b0 = (const float*)d_in[3];
    const float* W1 = (const float*)d_in[4];
    const float* b1 = (const float*)d_in[5];
    const float* W2 = (const float*)d_in[6];
    const float* b2 = (const float*)d_in[7];
    const float* W3 = (const float*)d_in[8];

    const int B = in_sizes[1] / 2;
    const int nchunks = (B + 15) / 16;

    int dev = 0, sms = 148;
    cudaGetDevice(&dev);
    cudaDeviceGetAttribute(&sms, cudaDevAttrMultiProcessorCount, dev);
    int grid = (nchunks + NW - 1) / NW;
    if (grid > sms) grid = sms;

    cudaFuncSetAttribute(lnn_mma, cudaFuncAttributeMaxDynamicSharedMemorySize,
                         SMEM_BYTES);
    lnn_mma<<<grid, TPB, SMEM_BYTES>>>((const float2*)x, W0, b0, W1, b1,
                                       W2, b2, W3, (float2*)d_out, B, nchunks);
}